// round 7
// baseline (speedup 1.0000x reference)
#include <cuda_runtime.h>
#include <cuda_bf16.h>
#include <math.h>
#include <cstdint>

#define Bsz 32
#define Ssz 576
#define Dsz 768
#define Gsz 24
#define Mrows (Bsz*Ssz)   // 18432
#define Ncols (3*Dsz)     // 2304

// ---------------- device scratch (allocation-free rule) ----------------
__device__ float g_q[Mrows*Dsz];
__device__ float g_k[Mrows*Dsz];
__device__ float g_v[Mrows*Dsz];
__device__ float g_sample[Mrows*2];
__device__ float g_weff[Dsz*60];
__device__ float g_beff[60];
__device__ unsigned int g_tile_ctr;
__device__ __nv_bfloat16 g_xhi[Mrows*Dsz];
__device__ __nv_bfloat16 g_xlo[Mrows*Dsz];
__device__ __nv_bfloat16 g_wthi[Ncols*Dsz];   // W^T [n][k]
__device__ __nv_bfloat16 g_wtlo[Ncols*Dsz];

__device__ __forceinline__ uint32_t smem_u32(const void* p) {
    uint32_t a;
    asm("{ .reg .u64 t; cvta.to.shared.u64 t, %1; cvt.u32.u64 %0, t; }" : "=r"(a) : "l"(p));
    return a;
}
__device__ __forceinline__ void cpa16(uint32_t d, const void* s) {
    asm volatile("cp.async.cg.shared.global [%0], [%1], 16;" :: "r"(d), "l"(s));
}
#define CP_COMMIT() asm volatile("cp.async.commit_group;" ::: "memory")
#define CP_WAIT(n)  asm volatile("cp.async.wait_group %0;" :: "n"(n) : "memory")

#define MMA16816(c, A, B) \
    asm volatile("mma.sync.aligned.m16n8k16.row.col.f32.bf16.bf16.f32 " \
        "{%0,%1,%2,%3},{%4,%5,%6,%7},{%8,%9},{%0,%1,%2,%3};" \
        : "+f"((c)[0]), "+f"((c)[1]), "+f"((c)[2]), "+f"((c)[3]) \
        : "r"((A)[0]), "r"((A)[1]), "r"((A)[2]), "r"((A)[3]), "r"((B)[0]), "r"((B)[1]))

__device__ __forceinline__ void ldsm_x4(uint32_t* r, uint32_t addr) {
    asm volatile("ldmatrix.sync.aligned.m8n8.x4.shared.b16 {%0,%1,%2,%3}, [%4];"
        : "=r"(r[0]), "=r"(r[1]), "=r"(r[2]), "=r"(r[3]) : "r"(addr));
}

// ---------------------------------------------------------------------------
// Prep 1: X fp32 -> bf16 hi/lo
// ---------------------------------------------------------------------------
__global__ __launch_bounds__(256) void prep_x(const float* __restrict__ X)
{
    const int t = blockIdx.x * 256 + threadIdx.x;
    const size_t base = (size_t)t * 8;
    float4 a = *(const float4*)&X[base];
    float4 b = *(const float4*)&X[base + 4];
    __nv_bfloat16 hi[8], lo[8];
    float v[8] = {a.x,a.y,a.z,a.w,b.x,b.y,b.z,b.w};
    #pragma unroll
    for (int i = 0; i < 8; i++) {
        hi[i] = __float2bfloat16(v[i]);
        lo[i] = __float2bfloat16(v[i] - __bfloat162float(hi[i]));
    }
    *(uint4*)&g_xhi[base] = *(uint4*)hi;
    *(uint4*)&g_xlo[base] = *(uint4*)lo;
}

// ---------------------------------------------------------------------------
// Prep 2: W [k][n] fp32 -> Wt hi/lo [n][k] bf16 (32x32 smem transpose)
// ---------------------------------------------------------------------------
__global__ __launch_bounds__(256) void prep_w(
    const float* __restrict__ Wq, const float* __restrict__ Wk, const float* __restrict__ Wv)
{
    __shared__ float ts[32][33];
    const int bx = blockIdx.x;
    const int by = blockIdx.y;
    const int which = bx / 24;
    const float* W = which == 0 ? Wq : (which == 1 ? Wk : Wv);
    const int nloc0 = (bx % 24) * 32;
    const int k0 = by * 32;
    const int tx = threadIdx.x % 32, ty = threadIdx.x / 32;

    #pragma unroll
    for (int r = ty; r < 32; r += 8)
        ts[r][tx] = W[(size_t)(k0 + r) * Dsz + nloc0 + tx];
    __syncthreads();
    #pragma unroll
    for (int r = ty; r < 32; r += 8) {
        float v = ts[tx][r];
        __nv_bfloat16 hi = __float2bfloat16(v);
        __nv_bfloat16 lo = __float2bfloat16(v - __bfloat162float(hi));
        size_t o = (size_t)(bx * 32 + r) * Dsz + k0 + tx;
        g_wthi[o] = hi;
        g_wtlo[o] = lo;
    }
}

// ---------------------------------------------------------------------------
// Prep 3 (grid 25): blocks 0..23 -> Weff (32 rows each);  block 24 -> beff
// (+ resets the GEMM tile counter for this launch/replay).
// ---------------------------------------------------------------------------
__global__ __launch_bounds__(256) void weff_kernel(
    const float* __restrict__ Wq, const float* __restrict__ Wk,
    const float* __restrict__ W1, const float* __restrict__ b1,
    const float* __restrict__ bq, const float* __restrict__ bk)
{
    const int tid = threadIdx.x;
    if (blockIdx.x == 24) {
        if (tid == 0) g_tile_ctr = 0;        // reset dynamic tile queue
        const int w = tid >> 5, lane = tid & 31;
        #pragma unroll 1
        for (int o = w; o < 60; o += 8) {
            float s = 0.f;
            #pragma unroll 4
            for (int j = lane; j < Dsz; j += 32) {
                s = fmaf(bq[j], W1[(size_t)j * 60 + o], s);
                s = fmaf(bk[j], W1[(size_t)(Dsz + j) * 60 + o], s);
            }
            #pragma unroll
            for (int t = 16; t > 0; t >>= 1) s += __shfl_xor_sync(0xffffffffu, s, t);
            if (lane == 0) g_beff[o] = b1[o] + s;
        }
        return;
    }

    __shared__ float As[32][33];
    __shared__ float Ws[32][64];
    const int tx = tid % 16, ty = tid / 16;
    const int k0 = blockIdx.x * 32;

    float acc[2][4];
    #pragma unroll
    for (int r = 0; r < 2; r++)
        #pragma unroll
        for (int j = 0; j < 4; j++) acc[r][j] = 0.f;

    #pragma unroll 1
    for (int p = 0; p < 2; p++) {
        const float* Wsrc = p ? Wk : Wq;
        const int w1off = p * Dsz;
        #pragma unroll 1
        for (int jc = 0; jc < Dsz; jc += 32) {
            {
                int r = tid >> 3, c4 = tid & 7;
                float4 a = *(const float4*)&Wsrc[(size_t)(k0 + r) * Dsz + jc + c4 * 4];
                As[c4*4+0][r] = a.x; As[c4*4+1][r] = a.y;
                As[c4*4+2][r] = a.z; As[c4*4+3][r] = a.w;
            }
            for (int e = tid; e < 32*64; e += 256) {
                int i = e >> 6, o = e & 63;
                Ws[i][o] = (o < 60) ? W1[(size_t)(w1off + jc + i) * 60 + o] : 0.f;
            }
            __syncthreads();
            #pragma unroll
            for (int i = 0; i < 32; i++) {
                float4 w = *(const float4*)&Ws[i][tx*4];
                float a0 = As[i][ty*2], a1 = As[i][ty*2+1];
                acc[0][0] = fmaf(a0, w.x, acc[0][0]);
                acc[0][1] = fmaf(a0, w.y, acc[0][1]);
                acc[0][2] = fmaf(a0, w.z, acc[0][2]);
                acc[0][3] = fmaf(a0, w.w, acc[0][3]);
                acc[1][0] = fmaf(a1, w.x, acc[1][0]);
                acc[1][1] = fmaf(a1, w.y, acc[1][1]);
                acc[1][2] = fmaf(a1, w.z, acc[1][2]);
                acc[1][3] = fmaf(a1, w.w, acc[1][3]);
            }
            __syncthreads();
        }
    }
    #pragma unroll
    for (int r = 0; r < 2; r++)
        #pragma unroll
        for (int j = 0; j < 4; j++) {
            int o = tx*4 + j;
            if (o < 60) g_weff[(size_t)(k0 + ty*2 + r) * 60 + o] = acc[r][j];
        }
}

// ---------------------------------------------------------------------------
// Kernel 1: persistent QKV GEMM, HMMA bf16x3, ldmatrix, 2-stage cp.async,
// dynamic tile queue (atomicAdd). 296 CTAs, 2/SM. Tile 128x128, KC=32.
// ---------------------------------------------------------------------------
#define GBM 128
#define GBN 128
#define KC 32
#define PADR 40
#define STAGE_BYTES 40960
#define NSTAGE 2
#define SMEM_GEMM (NSTAGE*STAGE_BYTES)
#define NTILES ((Mrows/GBM)*(Ncols/GBN))   // 144*18 = 2592
#define NBLK 296

__device__ __forceinline__ void load_chunk_g(uint32_t sb, int stage, int m0, int ng,
                                             int kk, int tid)
{
    const uint32_t s0 = sb + stage * STAGE_BYTES;
    #pragma unroll
    for (int it = 0; it < 2; it++) {
        int f = tid + it * 256;
        int r = f >> 2, j = f & 3;
        size_t go = (size_t)(m0 + r) * Dsz + kk + j * 8;
        uint32_t dst = s0 + (uint32_t)(r * PADR + j * 8) * 2;
        cpa16(dst,          &g_xhi[go]);
        cpa16(dst + 10240u, &g_xlo[go]);
    }
    #pragma unroll
    for (int it = 0; it < 2; it++) {
        int f = tid + it * 256;
        int r = f >> 2, j = f & 3;
        size_t go = (size_t)(ng + r) * Dsz + kk + j * 8;
        uint32_t dst = s0 + 20480u + (uint32_t)(r * PADR + j * 8) * 2;
        cpa16(dst,          &g_wthi[go]);
        cpa16(dst + 10240u, &g_wtlo[go]);
    }
}

__global__ __launch_bounds__(256, 2) void gemm_qkv_mma(
    const float* __restrict__ bq, const float* __restrict__ bk, const float* __restrict__ bv)
{
    extern __shared__ char smem[];
    __shared__ unsigned int s_tile;
    const uint32_t sb = smem_u32(smem);
    const int tid = threadIdx.x;
    const int wid = tid >> 5, lane = tid & 31;
    const int g = lane >> 2, tig = lane & 3;
    const int wm = wid & 1;
    const int wn = wid >> 1;

    const int la = (lane & 7) + ((lane >> 3) & 1) * 8;
    const int ka = (lane >> 4) * 8;
    const int lb = (lane & 7) + ((lane >> 4) & 1) * 8;
    const int kb = ((lane >> 3) & 1) * 8;
    const uint32_t aoffs = (uint32_t)(((wm * 64 + la) * PADR + ka) * 2);
    const uint32_t boffs = (uint32_t)(((wn * 32 + lb) * PADR + kb) * 2);

    for (;;) {
        if (tid == 0) s_tile = atomicAdd(&g_tile_ctr, 1u);
        __syncthreads();
        const unsigned int t = s_tile;
        if (t >= NTILES) break;
        const int m0 = (int)(t / 18) * GBM;
        const int ng = (int)(t % 18) * GBN;

        float acc[4][4][4];
        #pragma unroll
        for (int mt = 0; mt < 4; mt++)
            #pragma unroll
            for (int nt = 0; nt < 4; nt++)
                #pragma unroll
                for (int e = 0; e < 4; e++) acc[mt][nt][e] = 0.f;

        load_chunk_g(sb, 0, m0, ng, 0, tid);
        CP_COMMIT();

        #pragma unroll 1
        for (int c = 0; c < 24; c++) {
            if (c + 1 < 24) {
                load_chunk_g(sb, (c + 1) & 1, m0, ng, (c + 1) * KC, tid);
                CP_COMMIT();
                CP_WAIT(1);
            } else {
                CP_WAIT(0);
            }
            __syncthreads();

            const uint32_t stage0 = sb + (c & 1) * STAGE_BYTES;
            const uint32_t Ah = stage0 +     0u + aoffs;
            const uint32_t Al = stage0 + 10240u + aoffs;
            const uint32_t Bh = stage0 + 20480u + boffs;
            const uint32_t Bl = stage0 + 30720u + boffs;

            #pragma unroll
            for (int ks = 0; ks < KC; ks += 16) {
                const uint32_t ko = (uint32_t)(ks * 2);
                uint32_t af[4][4], bh[2][4], bl[2][4];
                #pragma unroll
                for (int mt = 0; mt < 4; mt++)
                    ldsm_x4(af[mt], Ah + ko + (uint32_t)(mt * 16 * PADR * 2));
                #pragma unroll
                for (int np = 0; np < 2; np++)
                    ldsm_x4(bh[np], Bh + ko + (uint32_t)(np * 16 * PADR * 2));
                #pragma unroll
                for (int mt = 0; mt < 4; mt++)
                    #pragma unroll
                    for (int np = 0; np < 2; np++) {
                        MMA16816(acc[mt][np*2+0], af[mt], &bh[np][0]);
                        MMA16816(acc[mt][np*2+1], af[mt], &bh[np][2]);
                    }
                #pragma unroll
                for (int np = 0; np < 2; np++)
                    ldsm_x4(bl[np], Bl + ko + (uint32_t)(np * 16 * PADR * 2));
                #pragma unroll
                for (int mt = 0; mt < 4; mt++)
                    #pragma unroll
                    for (int np = 0; np < 2; np++) {
                        MMA16816(acc[mt][np*2+0], af[mt], &bl[np][0]);
                        MMA16816(acc[mt][np*2+1], af[mt], &bl[np][2]);
                    }
                #pragma unroll
                for (int mt = 0; mt < 4; mt++)
                    ldsm_x4(af[mt], Al + ko + (uint32_t)(mt * 16 * PADR * 2));
                #pragma unroll
                for (int mt = 0; mt < 4; mt++)
                    #pragma unroll
                    for (int np = 0; np < 2; np++) {
                        MMA16816(acc[mt][np*2+0], af[mt], &bh[np][0]);
                        MMA16816(acc[mt][np*2+1], af[mt], &bh[np][2]);
                    }
            }
            __syncthreads();
        }

        const int which = ng / Dsz;
        const int nloc0 = ng - which * Dsz;
        const float* bias = which == 0 ? bq : (which == 1 ? bk : bv);
        float* OUT       = which == 0 ? g_q : (which == 1 ? g_k : g_v);

        #pragma unroll
        for (int mt = 0; mt < 4; mt++) {
            const int r0 = m0 + wm * 64 + mt * 16 + g;
            #pragma unroll
            for (int nt = 0; nt < 4; nt++) {
                const int nl = nloc0 + wn * 32 + nt * 8 + tig * 2;
                const float b0 = __ldg(&bias[nl]), b1 = __ldg(&bias[nl + 1]);
                float2 v0 = make_float2(acc[mt][nt][0] + b0, acc[mt][nt][1] + b1);
                float2 v1 = make_float2(acc[mt][nt][2] + b0, acc[mt][nt][3] + b1);
                *(float2*)&OUT[(size_t)r0       * Dsz + nl] = v0;
                *(float2*)&OUT[(size_t)(r0 + 8) * Dsz + nl] = v1;
            }
        }
        __syncthreads();   // protect stages + s_tile for next iteration
    }
}

// ---------------------------------------------------------------------------
// Kernel 2: MLP with folded fc1 (reads x directly). 64 rows/block, 288 blocks.
// ---------------------------------------------------------------------------
__global__ __launch_bounds__(256) void mlp_kernel(
    const float* __restrict__ X,
    const float* __restrict__ W2, const float* __restrict__ b2,
    const float* __restrict__ W3, const float* __restrict__ b3)
{
    __shared__ float smem[8192];
    float (*As)[65]  = (float(*)[65])smem;
    float (*Ws)[64]  = (float(*)[64])(smem + 2080);
    float (*H)[65]   = (float(*)[65])smem;
    float (*W2s)[64] = (float(*)[64])(smem + 4160);
    float *W3s = smem + 8000;
    float *b3s = smem + 8120;

    const int tid = threadIdx.x;
    const int tx = tid % 16;
    const int ty = tid / 16;
    const int row0 = blockIdx.x * 64;

    float acc[4][4];
    #pragma unroll
    for (int r = 0; r < 4; r++)
        #pragma unroll
        for (int j = 0; j < 4; j++) {
            int o = tx*4 + j;
            acc[r][j] = (o < 60) ? __ldg(&g_beff[o]) : 0.f;
        }

    #pragma unroll 1
    for (int kc = 0; kc < Dsz; kc += 32) {
        #pragma unroll
        for (int it = 0; it < 2; it++) {
            int f = tid + 256 * it;
            int r = f >> 3, c4 = f & 7;
            float4 a = *(const float4*)&X[(size_t)(row0 + r) * Dsz + kc + c4*4];
            As[c4*4+0][r] = a.x; As[c4*4+1][r] = a.y;
            As[c4*4+2][r] = a.z; As[c4*4+3][r] = a.w;
        }
        for (int e = tid; e < 32*64; e += 256) {
            int i = e >> 6, o = e & 63;
            Ws[i][o] = (o < 60) ? g_weff[(size_t)(kc + i) * 60 + o] : 0.f;
        }
        __syncthreads();
        #pragma unroll
        for (int i = 0; i < 32; i++) {
            float4 w = *(const float4*)&Ws[i][tx*4];
            float a[4];
            #pragma unroll
            for (int r = 0; r < 4; r++) a[r] = As[i][ty*4 + r];
            #pragma unroll
            for (int r = 0; r < 4; r++) {
                acc[r][0] = fmaf(a[r], w.x, acc[r][0]);
                acc[r][1] = fmaf(a[r], w.y, acc[r][1]);
                acc[r][2] = fmaf(a[r], w.z, acc[r][2]);
                acc[r][3] = fmaf(a[r], w.w, acc[r][3]);
            }
        }
        __syncthreads();
    }

    #pragma unroll
    for (int r = 0; r < 4; r++)
        #pragma unroll
        for (int j = 0; j < 4; j++) {
            int o = tx*4 + j;
            if (o < 60) H[o][ty*4 + r] = fmaxf(acc[r][j], 0.f);
        }
    for (int e = tid; e < 60*64; e += 256) {
        int i = e >> 6, o = e & 63;
        W2s[i][o] = (o < 60) ? W2[i*60 + o] : 0.f;
    }
    if (tid < 120) W3s[tid] = W3[tid];
    if (tid < 2)   b3s[tid] = b3[tid];
    __syncthreads();

    float acc2[4][4];
    #pragma unroll
    for (int r = 0; r < 4; r++)
        #pragma unroll
        for (int j = 0; j < 4; j++) {
            int o = tx*4 + j;
            acc2[r][j] = (o < 60) ? __ldg(&b2[o]) : 0.f;
        }
    #pragma unroll 4
    for (int i = 0; i < 60; i++) {
        float4 w = *(const float4*)&W2s[i][tx*4];
        float a[4];
        #pragma unroll
        for (int r = 0; r < 4; r++) a[r] = H[i][ty*4 + r];
        #pragma unroll
        for (int r = 0; r < 4; r++) {
            acc2[r][0] = fmaf(a[r], w.x, acc2[r][0]);
            acc2[r][1] = fmaf(a[r], w.y, acc2[r][1]);
            acc2[r][2] = fmaf(a[r], w.z, acc2[r][2]);
            acc2[r][3] = fmaf(a[r], w.w, acc2[r][3]);
        }
    }
    __syncthreads();
    #pragma unroll
    for (int r = 0; r < 4; r++)
        #pragma unroll
        for (int j = 0; j < 4; j++) {
            int o = tx*4 + j;
            if (o < 60) H[o][ty*4 + r] = fmaxf(acc2[r][j], 0.f);
        }
    __syncthreads();

    if (tid < 64) {
        float s0 = b3s[0], s1 = b3s[1];
        #pragma unroll 4
        for (int i = 0; i < 60; i++) {
            float h = H[i][tid];
            s0 = fmaf(h, W3s[i*2 + 0], s0);
            s1 = fmaf(h, W3s[i*2 + 1], s1);
        }
        size_t rr = (size_t)(row0 + tid) * 2;
        g_sample[rr + 0] = tanhf(s0);
        g_sample[rr + 1] = tanhf(s1);
    }
}

// ---------------------------------------------------------------------------
// Kernel 3: warp-per-row grid-sample + score + gate.
// ---------------------------------------------------------------------------
__global__ __launch_bounds__(256) void sample_attn_kernel(float* __restrict__ out)
{
    const int lane = threadIdx.x & 31;
    const int row  = blockIdx.x * 8 + (threadIdx.x >> 5);
    const int b = row / Ssz;
    const int s = row % Ssz;

    const size_t sbase = (size_t)b * Ssz * 2;
    const int p0 = 2*s, p1 = 2*s + 1;
    const float gxv = (p0 < Ssz) ? g_sample[sbase + (size_t)p0*2 + 0]
                                 : g_sample[sbase + (size_t)(p0 - Ssz)*2 + 1];
    const float gyv = (p1 < Ssz) ? g_sample[sbase + (size_t)p1*2 + 0]
                                 : g_sample[sbase + (size_t)(p1 - Ssz)*2 + 1];

    const float ix = ((gxv + 1.f) * (float)Gsz - 1.f) * 0.5f;
    const float iy = ((gyv + 1.f) * (float)Gsz - 1.f) * 0.5f;
    const float x0f = floorf(ix), y0f = floorf(iy);
    const float wx1 = ix - x0f, wx0 = 1.f - wx1;
    const float wy1 = iy - y0f, wy0 = 1.f - wy1;
    const int x0 = (int)x0f, y0 = (int)y0f;
    const int x1 = x0 + 1,   y1 = y0 + 1;

    float w[4];
    int   pos[4];
    {
        const int xs[4] = {x0, x1, x0, x1};
        const int ys[4] = {y0, y0, y1, y1};
        const float ws[4] = {wx0*wy0, wx1*wy0, wx0*wy1, wx1*wy1};
        #pragma unroll
        for (int c = 0; c < 4; c++) {
            bool v = (xs[c] >= 0) && (xs[c] <= Gsz-1) && (ys[c] >= 0) && (ys[c] <= Gsz-1);
            int xc = min(max(xs[c], 0), Gsz-1);
            int yc = min(max(ys[c], 0), Gsz-1);
            pos[c] = yc * Gsz + xc;
            w[c] = v ? ws[c] : 0.f;
        }
    }

    const float4* q4 = (const float4*)(g_q + (size_t)row * Dsz);
    const float4* k4 = (const float4*)(g_k + (size_t)b * Ssz * Dsz);
    const float4* v4 = (const float4*)(g_v + (size_t)b * Ssz * Dsz);

    float part = 0.f;
    float4 sv[6];
    #pragma unroll
    for (int j = 0; j < 6; j++) {
        const int d = lane + j * 32;
        const float4 q = q4[d];
        float4 sk = make_float4(0.f,0.f,0.f,0.f);
        float4 vv = make_float4(0.f,0.f,0.f,0.f);
        #pragma unroll
        for (int c = 0; c < 4; c++) {
            const float4 kk = k4[pos[c] * 192 + d];
            const float4 vx = v4[pos[c] * 192 + d];
            sk.x = fmaf(w[c], kk.x, sk.x); sk.y = fmaf(w[c], kk.y, sk.y);
            sk.z = fmaf(w[c], kk.z, sk.z); sk.w = fmaf(w[c], kk.w, sk.w);
            vv.x = fmaf(w[c], vx.x, vv.x); vv.y = fmaf(w[c], vx.y, vv.y);
            vv.z = fmaf(w[c], vx.z, vv.z); vv.w = fmaf(w[c], vx.w, vv.w);
        }
        part += q.x*sk.x + q.y*sk.y + q.z*sk.z + q.w*sk.w;
        sv[j] = vv;
    }

    #pragma unroll
    for (int o = 16; o > 0; o >>= 1)
        part += __shfl_xor_sync(0xffffffffu, part, o);
    const float g = 1.f / (1.f + expf(-0.01f * part));

    float4* o4 = (float4*)(out + (size_t)row * Dsz);
    #pragma unroll
    for (int j = 0; j < 6; j++) {
        float4 r = sv[j];
        r.x *= g; r.y *= g; r.z *= g; r.w *= g;
        o4[lane + j * 32] = r;
    }
}

// ---------------------------------------------------------------------------
extern "C" void kernel_launch(void* const* d_in, const int* in_sizes, int n_in,
                              void* d_out, int out_size)
{
    const float* x  = (const float*)d_in[0];
    const float* Wq = (const float*)d_in[2];
    const float* bq = (const float*)d_in[3];
    const float* Wk = (const float*)d_in[4];
    const float* bk = (const float*)d_in[5];
    const float* Wv = (const float*)d_in[6];
    const float* bv = (const float*)d_in[7];
    const float* W1 = (const float*)d_in[8];
    const float* b1 = (const float*)d_in[9];
    const float* W2 = (const float*)d_in[10];
    const float* b2 = (const float*)d_in[11];
    const float* W3 = (const float*)d_in[12];
    const float* b3 = (const float*)d_in[13];

    cudaFuncSetAttribute(gemm_qkv_mma, cudaFuncAttributeMaxDynamicSharedMemorySize, SMEM_GEMM);

    prep_x<<<Mrows * Dsz / (256 * 8), 256>>>(x);                         // 1
    prep_w<<<dim3(72, 24), 256>>>(Wq, Wk, Wv);                           // 2
    weff_kernel<<<25, 256>>>(Wq, Wk, W1, b1, bq, bk);                    // 3 (also resets tile ctr)
    gemm_qkv_mma<<<NBLK, 256, SMEM_GEMM>>>(bq, bk, bv);                  // 4 (profiled)
    mlp_kernel<<<Mrows / 64, 256>>>(x, W2, b2, W3, b3);                  // 5
    sample_attn_kernel<<<Mrows / 8, 256>>>((float*)d_out);               // 6
}

// round 9
// speedup vs baseline: 1.0236x; 1.0236x over previous
#include <cuda_runtime.h>
#include <cuda_bf16.h>
#include <math.h>
#include <cstdint>

#define Bsz 32
#define Ssz 576
#define Dsz 768
#define Gsz 24
#define Mrows (Bsz*Ssz)   // 18432
#define Ncols (3*Dsz)     // 2304

// ---------------- device scratch (allocation-free rule) ----------------
__device__ float g_q[Mrows*Dsz];
__device__ float g_k[Mrows*Dsz];
__device__ float g_v[Mrows*Dsz];
__device__ float g_sample[Mrows*2];
__device__ float g_weff[Dsz*60];
__device__ float g_beff[60];
__device__ unsigned int g_tile_ctr;
__device__ __nv_bfloat16 g_xhi[Mrows*Dsz];
__device__ __nv_bfloat16 g_xlo[Mrows*Dsz];
__device__ __nv_bfloat16 g_wthi[Ncols*Dsz];   // W^T [n][k]
__device__ __nv_bfloat16 g_wtlo[Ncols*Dsz];

__device__ __forceinline__ uint32_t smem_u32(const void* p) {
    uint32_t a;
    asm("{ .reg .u64 t; cvta.to.shared.u64 t, %1; cvt.u32.u64 %0, t; }" : "=r"(a) : "l"(p));
    return a;
}
__device__ __forceinline__ void cpa16(uint32_t d, const void* s) {
    asm volatile("cp.async.cg.shared.global [%0], [%1], 16;" :: "r"(d), "l"(s));
}
#define MBARRIER_INIT(addr, cnt) \
    asm volatile("mbarrier.init.shared.b64 [%0], %1;" :: "r"((uint32_t)(addr)), "r"((uint32_t)(cnt)) : "memory")
#define MBARRIER_ARRIVE(addr) \
    asm volatile("mbarrier.arrive.shared.b64 _, [%0];" :: "r"((uint32_t)(addr)) : "memory")
// .noinc: arrival counts against the init expected count (pre-counted pattern).
#define CPASYNC_MBAR_ARRIVE_NOINC(addr) \
    asm volatile("cp.async.mbarrier.arrive.noinc.shared::cta.b64 [%0];" :: "r"((uint32_t)(addr)) : "memory")
#define MBARRIER_WAIT_PARITY(mb, par) do { \
    uint32_t _m = (uint32_t)(mb), _p = (uint32_t)(par), _d; \
    asm volatile("{\n\t.reg .pred p;\n\tmbarrier.try_wait.parity.acquire.cta.shared::cta.b64 p, [%1], %2;\n\tselp.b32 %0, 1, 0, p;\n\t}" \
        : "=r"(_d) : "r"(_m), "r"(_p) : "memory"); \
    if (!_d) { \
        asm volatile("{\n\t.reg .pred P1;\n\tWL_%=:\n\tmbarrier.try_wait.parity.acquire.cta.shared::cta.b64 P1, [%0], %1, 0x989680;\n\t@P1 bra.uni WD_%=;\n\tbra.uni WL_%=;\n\tWD_%=:\n\t}" \
            :: "r"(_m), "r"(_p) : "memory"); \
    } } while (0)

#define MMA16816(c, A, B) \
    asm volatile("mma.sync.aligned.m16n8k16.row.col.f32.bf16.bf16.f32 " \
        "{%0,%1,%2,%3},{%4,%5,%6,%7},{%8,%9},{%0,%1,%2,%3};" \
        : "+f"((c)[0]), "+f"((c)[1]), "+f"((c)[2]), "+f"((c)[3]) \
        : "r"((A)[0]), "r"((A)[1]), "r"((A)[2]), "r"((A)[3]), "r"((B)[0]), "r"((B)[1]))

__device__ __forceinline__ void ldsm_x4(uint32_t* r, uint32_t addr) {
    asm volatile("ldmatrix.sync.aligned.m8n8.x4.shared.b16 {%0,%1,%2,%3}, [%4];"
        : "=r"(r[0]), "=r"(r[1]), "=r"(r[2]), "=r"(r[3]) : "r"(addr));
}

// ---------------------------------------------------------------------------
// Fused prep: blocks [0,6912) prep_x; [6912,8640) prep_w
// ---------------------------------------------------------------------------
#define PREPX_BLOCKS 6912
#define PREPW_BLOCKS 1728
#define PREP_GRID (PREPX_BLOCKS + PREPW_BLOCKS)

__global__ __launch_bounds__(256) void fused_prep(
    const float* __restrict__ X,
    const float* __restrict__ Wq, const float* __restrict__ Wk, const float* __restrict__ Wv)
{
    const int bid = blockIdx.x;
    const int tid = threadIdx.x;

    if (bid < PREPX_BLOCKS) {
        const int t = bid * 256 + tid;
        const size_t base = (size_t)t * 8;
        float4 a = *(const float4*)&X[base];
        float4 b = *(const float4*)&X[base + 4];
        __nv_bfloat16 hi[8], lo[8];
        float v[8] = {a.x,a.y,a.z,a.w,b.x,b.y,b.z,b.w};
        #pragma unroll
        for (int i = 0; i < 8; i++) {
            hi[i] = __float2bfloat16(v[i]);
            lo[i] = __float2bfloat16(v[i] - __bfloat162float(hi[i]));
        }
        *(uint4*)&g_xhi[base] = *(uint4*)hi;
        *(uint4*)&g_xlo[base] = *(uint4*)lo;
        return;
    }

    __shared__ float ts[32][33];
    const int b2 = bid - PREPX_BLOCKS;
    const int bx = b2 % 72;
    const int by = b2 / 72;
    const int which = bx / 24;
    const float* W = which == 0 ? Wq : (which == 1 ? Wk : Wv);
    const int nloc0 = (bx % 24) * 32;
    const int k0 = by * 32;
    const int tx = tid % 32, ty = tid / 32;

    #pragma unroll
    for (int r = ty; r < 32; r += 8)
        ts[r][tx] = W[(size_t)(k0 + r) * Dsz + nloc0 + tx];
    __syncthreads();
    #pragma unroll
    for (int r = ty; r < 32; r += 8) {
        float v = ts[tx][r];
        __nv_bfloat16 hi = __float2bfloat16(v);
        __nv_bfloat16 lo = __float2bfloat16(v - __bfloat162float(hi));
        size_t o = (size_t)(bx * 32 + r) * Dsz + k0 + tx;
        g_wthi[o] = hi;
        g_wtlo[o] = lo;
    }
}

// ---------------------------------------------------------------------------
// weff/beff (grid 25): blocks 0..23 -> Weff (32 rows each); block 24 -> beff
// (+ resets the GEMM tile counter for this launch/replay).
// ---------------------------------------------------------------------------
__global__ __launch_bounds__(256) void weff_kernel(
    const float* __restrict__ Wq, const float* __restrict__ Wk,
    const float* __restrict__ W1, const float* __restrict__ b1,
    const float* __restrict__ bq, const float* __restrict__ bk)
{
    const int tid = threadIdx.x;
    if (blockIdx.x == 24) {
        if (tid == 0) g_tile_ctr = 0;
        const int w = tid >> 5, lane = tid & 31;
        #pragma unroll 1
        for (int o = w; o < 60; o += 8) {
            float s = 0.f;
            #pragma unroll 4
            for (int j = lane; j < Dsz; j += 32) {
                s = fmaf(bq[j], W1[(size_t)j * 60 + o], s);
                s = fmaf(bk[j], W1[(size_t)(Dsz + j) * 60 + o], s);
            }
            #pragma unroll
            for (int t = 16; t > 0; t >>= 1) s += __shfl_xor_sync(0xffffffffu, s, t);
            if (lane == 0) g_beff[o] = b1[o] + s;
        }
        return;
    }

    __shared__ float As[32][33];
    __shared__ float Ws[32][64];
    const int tx = tid % 16, ty = tid / 16;
    const int k0 = blockIdx.x * 32;

    float acc[2][4];
    #pragma unroll
    for (int r = 0; r < 2; r++)
        #pragma unroll
        for (int j = 0; j < 4; j++) acc[r][j] = 0.f;

    #pragma unroll 1
    for (int p = 0; p < 2; p++) {
        const float* Wsrc = p ? Wk : Wq;
        const int w1off = p * Dsz;
        #pragma unroll 1
        for (int jc = 0; jc < Dsz; jc += 32) {
            {
                int r = tid >> 3, c4 = tid & 7;
                float4 a = *(const float4*)&Wsrc[(size_t)(k0 + r) * Dsz + jc + c4 * 4];
                As[c4*4+0][r] = a.x; As[c4*4+1][r] = a.y;
                As[c4*4+2][r] = a.z; As[c4*4+3][r] = a.w;
            }
            for (int e = tid; e < 32*64; e += 256) {
                int i = e >> 6, o = e & 63;
                Ws[i][o] = (o < 60) ? W1[(size_t)(w1off + jc + i) * 60 + o] : 0.f;
            }
            __syncthreads();
            #pragma unroll
            for (int i = 0; i < 32; i++) {
                float4 w = *(const float4*)&Ws[i][tx*4];
                float a0 = As[i][ty*2], a1 = As[i][ty*2+1];
                acc[0][0] = fmaf(a0, w.x, acc[0][0]);
                acc[0][1] = fmaf(a0, w.y, acc[0][1]);
                acc[0][2] = fmaf(a0, w.z, acc[0][2]);
                acc[0][3] = fmaf(a0, w.w, acc[0][3]);
                acc[1][0] = fmaf(a1, w.x, acc[1][0]);
                acc[1][1] = fmaf(a1, w.y, acc[1][1]);
                acc[1][2] = fmaf(a1, w.z, acc[1][2]);
                acc[1][3] = fmaf(a1, w.w, acc[1][3]);
            }
            __syncthreads();
        }
    }
    #pragma unroll
    for (int r = 0; r < 2; r++)
        #pragma unroll
        for (int j = 0; j < 4; j++) {
            int o = tx*4 + j;
            if (o < 60) g_weff[(size_t)(k0 + ty*2 + r) * 60 + o] = acc[r][j];
        }
}

// ---------------------------------------------------------------------------
// Kernel 1: warp-specialized persistent QKV GEMM (HMMA bf16x3).
// 1 block/SM, 544 thr = 16 consumer warps (4x4, warp tile 64x32 over a
// 256x128 block tile) + 1 producer warp. 3-stage mbarrier ring, KC=32.
// smem: [0..48) mbarriers (full/empty per stage), stages at +128.
// Stage: Ah[0,20480) Al[20480,40960) Bh[40960,51200) Bl[51200,61440)
// ---------------------------------------------------------------------------
#define GBM 256
#define GBN 128
#define KC 32
#define PADR 40
#define STAGE_BYTES 61440
#define NST 3
#define SMEM_GEMM (128 + NST*STAGE_BYTES)
#define NTILES ((Mrows/GBM)*(Ncols/GBN))   // 72*18 = 1296
#define NBLK 148
#define NCHUNK 24

__global__ __launch_bounds__(544, 1) void gemm_ws(
    const float* __restrict__ bq, const float* __restrict__ bk, const float* __restrict__ bv)
{
    extern __shared__ char smem[];
    __shared__ unsigned int s_tile;
    const uint32_t sb = smem_u32(smem);
    const uint32_t stbase = sb + 128;
    const int tid = threadIdx.x;
    const int wid = tid >> 5, lane = tid & 31;
    const int g = lane >> 2, tig = lane & 3;

    if (tid == 0) {
        #pragma unroll
        for (int s = 0; s < NST; s++) {
            MBARRIER_INIT(sb + s*16,     32);   // full[s]: 32 producer-lane noinc arrives
            MBARRIER_INIT(sb + s*16 + 8, 16);   // empty[s]: 16 consumer-warp arrives
        }
    }
    __syncthreads();

    const int wm = wid & 3;
    const int wn = wid >> 2;
    const int la = (lane & 7) + ((lane >> 3) & 1) * 8;
    const int ka = (lane >> 4) * 8;
    const int lb = (lane & 7) + ((lane >> 4) & 1) * 8;
    const int kb = ((lane >> 3) & 1) * 8;
    const uint32_t aoffs = (uint32_t)(((wm * 64 + la) * PADR + ka) * 2);
    const uint32_t boffs = (uint32_t)(((wn * 32 + lb) * PADR + kb) * 2);

    int cs = 0, cph = 0;      // consumer cursor
    int ps = 0, pph = 1;      // producer cursor (phase 1: first empty-wait passes)

    for (;;) {
        if (tid == 0) s_tile = atomicAdd(&g_tile_ctr, 1u);
        __syncthreads();
        const unsigned int t = s_tile;
        if (t >= NTILES) break;
        const int m0 = (int)(t / 18) * GBM;
        const int ng = (int)(t % 18) * GBN;

        if (wid == 16) {
            // ================= PRODUCER =================
            #pragma unroll 1
            for (int c = 0; c < NCHUNK; c++) {
                MBARRIER_WAIT_PARITY(sb + ps*16 + 8, pph);
                const uint32_t s0 = stbase + ps * STAGE_BYTES;
                const int kk = c * KC;
                #pragma unroll 4
                for (int i = 0; i < 32; i++) {
                    int f = lane + i * 32;
                    int r = f >> 2, j = f & 3;
                    size_t go = (size_t)(m0 + r) * Dsz + kk + j * 8;
                    uint32_t dst = s0 + (uint32_t)(r * PADR + j * 8) * 2;
                    cpa16(dst,          &g_xhi[go]);
                    cpa16(dst + 20480u, &g_xlo[go]);
                }
                #pragma unroll 4
                for (int i = 0; i < 16; i++) {
                    int f = lane + i * 32;
                    int r = f >> 2, j = f & 3;
                    size_t go = (size_t)(ng + r) * Dsz + kk + j * 8;
                    uint32_t dst = s0 + 40960u + (uint32_t)(r * PADR + j * 8) * 2;
                    cpa16(dst,          &g_wthi[go]);
                    cpa16(dst + 10240u, &g_wtlo[go]);
                }
                CPASYNC_MBAR_ARRIVE_NOINC(sb + ps*16);
                if (++ps == NST) { ps = 0; pph ^= 1; }
            }
        } else {
            // ================= CONSUMER =================
            float acc[4][4][4];
            #pragma unroll
            for (int mt = 0; mt < 4; mt++)
                #pragma unroll
                for (int nt = 0; nt < 4; nt++)
                    #pragma unroll
                    for (int e = 0; e < 4; e++) acc[mt][nt][e] = 0.f;

            #pragma unroll 1
            for (int c = 0; c < NCHUNK; c++) {
                MBARRIER_WAIT_PARITY(sb + cs*16, cph);
                const uint32_t s0 = stbase + cs * STAGE_BYTES;
                const uint32_t Ah = s0 +     0u + aoffs;
                const uint32_t Al = s0 + 20480u + aoffs;
                const uint32_t Bh = s0 + 40960u + boffs;
                const uint32_t Bl = s0 + 51200u + boffs;

                #pragma unroll
                for (int ks = 0; ks < KC; ks += 16) {
                    const uint32_t ko = (uint32_t)(ks * 2);
                    uint32_t af[4][4], bh[2][4], bl[2][4];
                    #pragma unroll
                    for (int mt = 0; mt < 4; mt++)
                        ldsm_x4(af[mt], Ah + ko + (uint32_t)(mt * 16 * PADR * 2));
                    #pragma unroll
                    for (int np = 0; np < 2; np++)
                        ldsm_x4(bh[np], Bh + ko + (uint32_t)(np * 16 * PADR * 2));
                    #pragma unroll
                    for (int mt = 0; mt < 4; mt++)
                        #pragma unroll
                        for (int np = 0; np < 2; np++) {
                            MMA16816(acc[mt][np*2+0], af[mt], &bh[np][0]);
                            MMA16816(acc[mt][np*2+1], af[mt], &bh[np][2]);
                        }
                    #pragma unroll
                    for (int np = 0; np < 2; np++)
                        ldsm_x4(bl[np], Bl + ko + (uint32_t)(np * 16 * PADR * 2));
                    #pragma unroll
                    for (int mt = 0; mt < 4; mt++)
                        #pragma unroll
                        for (int np = 0; np < 2; np++) {
                            MMA16816(acc[mt][np*2+0], af[mt], &bl[np][0]);
                            MMA16816(acc[mt][np*2+1], af[mt], &bl[np][2]);
                        }
                    #pragma unroll
                    for (int mt = 0; mt < 4; mt++)
                        ldsm_x4(af[mt], Al + ko + (uint32_t)(mt * 16 * PADR * 2));
                    #pragma unroll
                    for (int mt = 0; mt < 4; mt++)
                        #pragma unroll
                        for (int np = 0; np < 2; np++) {
                            MMA16816(acc[mt][np*2+0], af[mt], &bh[np][0]);
                            MMA16816(acc[mt][np*2+1], af[mt], &bh[np][2]);
                        }
                }
                if (lane == 0) MBARRIER_ARRIVE(sb + cs*16 + 8);
                if (++cs == NST) { cs = 0; cph ^= 1; }
            }

            const int which = ng / Dsz;
            const int nloc0 = ng - which * Dsz;
            const float* bias = which == 0 ? bq : (which == 1 ? bk : bv);
            float* OUT       = which == 0 ? g_q : (which == 1 ? g_k : g_v);
            #pragma unroll
            for (int mt = 0; mt < 4; mt++) {
                const int r0 = m0 + wm * 64 + mt * 16 + g;
                #pragma unroll
                for (int nt = 0; nt < 4; nt++) {
                    const int nl = nloc0 + wn * 32 + nt * 8 + tig * 2;
                    const float b0 = __ldg(&bias[nl]), b1 = __ldg(&bias[nl + 1]);
                    float2 v0 = make_float2(acc[mt][nt][0] + b0, acc[mt][nt][1] + b1);
                    float2 v1 = make_float2(acc[mt][nt][2] + b0, acc[mt][nt][3] + b1);
                    *(float2*)&OUT[(size_t)r0       * Dsz + nl] = v0;
                    *(float2*)&OUT[(size_t)(r0 + 8) * Dsz + nl] = v1;
                }
            }
        }
        __syncthreads();
    }
}

// ---------------------------------------------------------------------------
// Kernel 2: MLP with folded fc1 (reads x directly). 64 rows/block, 288 blocks.
// ---------------------------------------------------------------------------
__global__ __launch_bounds__(256) void mlp_kernel(
    const float* __restrict__ X,
    const float* __restrict__ W2, const float* __restrict__ b2,
    const float* __restrict__ W3, const float* __restrict__ b3)
{
    __shared__ float smem[8192];
    float (*As)[65]  = (float(*)[65])smem;
    float (*Ws)[64]  = (float(*)[64])(smem + 2080);
    float (*H)[65]   = (float(*)[65])smem;
    float (*W2s)[64] = (float(*)[64])(smem + 4160);
    float *W3s = smem + 8000;
    float *b3s = smem + 8120;

    const int tid = threadIdx.x;
    const int tx = tid % 16;
    const int ty = tid / 16;
    const int row0 = blockIdx.x * 64;

    float acc[4][4];
    #pragma unroll
    for (int r = 0; r < 4; r++)
        #pragma unroll
        for (int j = 0; j < 4; j++) {
            int o = tx*4 + j;
            acc[r][j] = (o < 60) ? __ldg(&g_beff[o]) : 0.f;
        }

    #pragma unroll 1
    for (int kc = 0; kc < Dsz; kc += 32) {
        #pragma unroll
        for (int it = 0; it < 2; it++) {
            int f = tid + 256 * it;
            int r = f >> 3, c4 = f & 7;
            float4 a = *(const float4*)&X[(size_t)(row0 + r) * Dsz + kc + c4*4];
            As[c4*4+0][r] = a.x; As[c4*4+1][r] = a.y;
            As[c4*4+2][r] = a.z; As[c4*4+3][r] = a.w;
        }
        for (int e = tid; e < 32*64; e += 256) {
            int i = e >> 6, o = e & 63;
            Ws[i][o] = (o < 60) ? g_weff[(size_t)(kc + i) * 60 + o] : 0.f;
        }
        __syncthreads();
        #pragma unroll
        for (int i = 0; i < 32; i++) {
            float4 w = *(const float4*)&Ws[i][tx*4];
            float a[4];
            #pragma unroll
            for (int r = 0; r < 4; r++) a[r] = As[i][ty*4 + r];
            #pragma unroll
            for (int r = 0; r < 4; r++) {
                acc[r][0] = fmaf(a[r], w.x, acc[r][0]);
                acc[r][1] = fmaf(a[r], w.y, acc[r][1]);
                acc[r][2] = fmaf(a[r], w.z, acc[r][2]);
                acc[r][3] = fmaf(a[r], w.w, acc[r][3]);
            }
        }
        __syncthreads();
    }

    #pragma unroll
    for (int r = 0; r < 4; r++)
        #pragma unroll
        for (int j = 0; j < 4; j++) {
            int o = tx*4 + j;
            if (o < 60) H[o][ty*4 + r] = fmaxf(acc[r][j], 0.f);
        }
    for (int e = tid; e < 60*64; e += 256) {
        int i = e >> 6, o = e & 63;
        W2s[i][o] = (o < 60) ? W2[i*60 + o] : 0.f;
    }
    if (tid < 120) W3s[tid] = W3[tid];
    if (tid < 2)   b3s[tid] = b3[tid];
    __syncthreads();

    float acc2[4][4];
    #pragma unroll
    for (int r = 0; r < 4; r++)
        #pragma unroll
        for (int j = 0; j < 4; j++) {
            int o = tx*4 + j;
            acc2[r][j] = (o < 60) ? __ldg(&b2[o]) : 0.f;
        }
    #pragma unroll 4
    for (int i = 0; i < 60; i++) {
        float4 w = *(const float4*)&W2s[i][tx*4];
        float a[4];
        #pragma unroll
        for (int r = 0; r < 4; r++) a[r] = H[i][ty*4 + r];
        #pragma unroll
        for (int r = 0; r < 4; r++) {
            acc2[r][0] = fmaf(a[r], w.x, acc2[r][0]);
            acc2[r][1] = fmaf(a[r], w.y, acc2[r][1]);
            acc2[r][2] = fmaf(a[r], w.z, acc2[r][2]);
            acc2[r][3] = fmaf(a[r], w.w, acc2[r][3]);
        }
    }
    __syncthreads();
    #pragma unroll
    for (int r = 0; r < 4; r++)
        #pragma unroll
        for (int j = 0; j < 4; j++) {
            int o = tx*4 + j;
            if (o < 60) H[o][ty*4 + r] = fmaxf(acc2[r][j], 0.f);
        }
    __syncthreads();

    if (tid < 64) {
        float s0 = b3s[0], s1 = b3s[1];
        #pragma unroll 4
        for (int i = 0; i < 60; i++) {
            float h = H[i][tid];
            s0 = fmaf(h, W3s[i*2 + 0], s0);
            s1 = fmaf(h, W3s[i*2 + 1], s1);
        }
        size_t rr = (size_t)(row0 + tid) * 2;
        g_sample[rr + 0] = tanhf(s0);
        g_sample[rr + 1] = tanhf(s1);
    }
}

// ---------------------------------------------------------------------------
// Kernel 3: warp-per-row grid-sample + score + gate.
// ---------------------------------------------------------------------------
__global__ __launch_bounds__(256) void sample_attn_kernel(float* __restrict__ out)
{
    const int lane = threadIdx.x & 31;
    const int row  = blockIdx.x * 8 + (threadIdx.x >> 5);
    const int b = row / Ssz;
    const int s = row % Ssz;

    const size_t sbase = (size_t)b * Ssz * 2;
    const int p0 = 2*s, p1 = 2*s + 1;
    const float gxv = (p0 < Ssz) ? g_sample[sbase + (size_t)p0*2 + 0]
                                 : g_sample[sbase + (size_t)(p0 - Ssz)*2 + 1];
    const float gyv = (p1 < Ssz) ? g_sample[sbase + (size_t)p1*2 + 0]
                                 : g_sample[sbase + (size_t)(p1 - Ssz)*2 + 1];

    const float ix = ((gxv + 1.f) * (float)Gsz - 1.f) * 0.5f;
    const float iy = ((gyv + 1.f) * (float)Gsz - 1.f) * 0.5f;
    const float x0f = floorf(ix), y0f = floorf(iy);
    const float wx1 = ix - x0f, wx0 = 1.f - wx1;
    const float wy1 = iy - y0f, wy0 = 1.f - wy1;
    const int x0 = (int)x0f, y0 = (int)y0f;
    const int x1 = x0 + 1,   y1 = y0 + 1;

    float w[4];
    int   pos[4];
    {
        const int xs[4] = {x0, x1, x0, x1};
        const int ys[4] = {y0, y0, y1, y1};
        const float ws[4] = {wx0*wy0, wx1*wy0, wx0*wy1, wx1*wy1};
        #pragma unroll
        for (int c = 0; c < 4; c++) {
            bool v = (xs[c] >= 0) && (xs[c] <= Gsz-1) && (ys[c] >= 0) && (ys[c] <= Gsz-1);
            int xc = min(max(xs[c], 0), Gsz-1);
            int yc = min(max(ys[c], 0), Gsz-1);
            pos[c] = yc * Gsz + xc;
            w[c] = v ? ws[c] : 0.f;
        }
    }

    const float4* q4 = (const float4*)(g_q + (size_t)row * Dsz);
    const float4* k4 = (const float4*)(g_k + (size_t)b * Ssz * Dsz);
    const float4* v4 = (const float4*)(g_v + (size_t)b * Ssz * Dsz);

    float part = 0.f;
    float4 sv[6];
    #pragma unroll
    for (int j = 0; j < 6; j++) {
        const int d = lane + j * 32;
        const float4 q = q4[d];
        float4 sk = make_float4(0.f,0.f,0.f,0.f);
        float4 vv = make_float4(0.f,0.f,0.f,0.f);
        #pragma unroll
        for (int c = 0; c < 4; c++) {
            const float4 kk = k4[pos[c] * 192 + d];
            const float4 vx = v4[pos[c] * 192 + d];
            sk.x = fmaf(w[c], kk.x, sk.x); sk.y = fmaf(w[c], kk.y, sk.y);
            sk.z = fmaf(w[c], kk.z, sk.z); sk.w = fmaf(w[c], kk.w, sk.w);
            vv.x = fmaf(w[c], vx.x, vv.x); vv.y = fmaf(w[c], vx.y, vv.y);
            vv.z = fmaf(w[c], vx.z, vv.z); vv.w = fmaf(w[c], vx.w, vv.w);
        }
        part += q.x*sk.x + q.y*sk.y + q.z*sk.z + q.w*sk.w;
        sv[j] = vv;
    }

    #pragma unroll
    for (int o = 16; o > 0; o >>= 1)
        part += __shfl_xor_sync(0xffffffffu, part, o);
    const float g = 1.f / (1.f + expf(-0.01f * part));

    float4* o4 = (float4*)(out + (size_t)row * Dsz);
    #pragma unroll
    for (int j = 0; j < 6; j++) {
        float4 r = sv[j];
        r.x *= g; r.y *= g; r.z *= g; r.w *= g;
        o4[lane + j * 32] = r;
    }
}

// ---------------------------------------------------------------------------
extern "C" void kernel_launch(void* const* d_in, const int* in_sizes, int n_in,
                              void* d_out, int out_size)
{
    const float* x  = (const float*)d_in[0];
    const float* Wq = (const float*)d_in[2];
    const float* bq = (const float*)d_in[3];
    const float* Wk = (const float*)d_in[4];
    const float* bk = (const float*)d_in[5];
    const float* Wv = (const float*)d_in[6];
    const float* bv = (const float*)d_in[7];
    const float* W1 = (const float*)d_in[8];
    const float* b1 = (const float*)d_in[9];
    const float* W2 = (const float*)d_in[10];
    const float* b2 = (const float*)d_in[11];
    const float* W3 = (const float*)d_in[12];
    const float* b3 = (const float*)d_in[13];

    cudaFuncSetAttribute(gemm_ws, cudaFuncAttributeMaxDynamicSharedMemorySize, SMEM_GEMM);

    fused_prep<<<PREP_GRID, 256>>>(x, Wq, Wk, Wv);                     // 1
    weff_kernel<<<25, 256>>>(Wq, Wk, W1, b1, bq, bk);                  // 2 (resets tile ctr)
    mlp_kernel<<<Mrows / 64, 256>>>(x, W2, b2, W3, b3);                // 3
    gemm_ws<<<NBLK, 544, SMEM_GEMM>>>(bq, bk, bv);                     // 4 (profiled)
    sample_attn_kernel<<<Mrows / 8, 256>>>((float*)d_out);             // 5
}

// round 10
// speedup vs baseline: 1.1012x; 1.0758x over previous
#include <cuda_runtime.h>
#include <cuda_bf16.h>
#include <math.h>
#include <cstdint>

#define Bsz 32
#define Ssz 576
#define Dsz 768
#define Gsz 24
#define Mrows (Bsz*Ssz)   // 18432
#define Ncols (3*Dsz)     // 2304

// ---------------- device scratch (allocation-free rule) ----------------
__device__ float g_q[Mrows*Dsz];
__device__ float g_k[Mrows*Dsz];
__device__ float g_v[Mrows*Dsz];
__device__ float g_sample[Mrows*2];
__device__ float g_h1[Mrows*64];
__device__ float g_beff[64];
__device__ unsigned int g_tile_ctr;
__device__ __nv_bfloat16 g_xhi[Mrows*Dsz];
__device__ __nv_bfloat16 g_xlo[Mrows*Dsz];
__device__ __nv_bfloat16 g_wthi[Ncols*Dsz];    // [Wq|Wk|Wv]^T [n][k]
__device__ __nv_bfloat16 g_wtlo[Ncols*Dsz];
__device__ __nv_bfloat16 g_wehi[64*Dsz];       // Weff^T [o][k]
__device__ __nv_bfloat16 g_welo[64*Dsz];

__device__ __forceinline__ uint32_t smem_u32(const void* p) {
    uint32_t a;
    asm("{ .reg .u64 t; cvta.to.shared.u64 t, %1; cvt.u32.u64 %0, t; }" : "=r"(a) : "l"(p));
    return a;
}
__device__ __forceinline__ void cpa16(uint32_t d, const void* s) {
    asm volatile("cp.async.cg.shared.global [%0], [%1], 16;" :: "r"(d), "l"(s));
}
#define MBARRIER_INIT(addr, cnt) \
    asm volatile("mbarrier.init.shared.b64 [%0], %1;" :: "r"((uint32_t)(addr)), "r"((uint32_t)(cnt)) : "memory")
#define MBARRIER_ARRIVE(addr) \
    asm volatile("mbarrier.arrive.shared.b64 _, [%0];" :: "r"((uint32_t)(addr)) : "memory")
#define CPASYNC_MBAR_ARRIVE_NOINC(addr) \
    asm volatile("cp.async.mbarrier.arrive.noinc.shared::cta.b64 [%0];" :: "r"((uint32_t)(addr)) : "memory")
#define MBARRIER_WAIT_PARITY(mb, par) do { \
    uint32_t _m = (uint32_t)(mb), _p = (uint32_t)(par), _d; \
    asm volatile("{\n\t.reg .pred p;\n\tmbarrier.try_wait.parity.acquire.cta.shared::cta.b64 p, [%1], %2;\n\tselp.b32 %0, 1, 0, p;\n\t}" \
        : "=r"(_d) : "r"(_m), "r"(_p) : "memory"); \
    if (!_d) { \
        asm volatile("{\n\t.reg .pred P1;\n\tWL_%=:\n\tmbarrier.try_wait.parity.acquire.cta.shared::cta.b64 P1, [%0], %1, 0x989680;\n\t@P1 bra.uni WD_%=;\n\tbra.uni WL_%=;\n\tWD_%=:\n\t}" \
            :: "r"(_m), "r"(_p) : "memory"); \
    } } while (0)

#define MMA16816(c, A, B) \
    asm volatile("mma.sync.aligned.m16n8k16.row.col.f32.bf16.bf16.f32 " \
        "{%0,%1,%2,%3},{%4,%5,%6,%7},{%8,%9},{%0,%1,%2,%3};" \
        : "+f"((c)[0]), "+f"((c)[1]), "+f"((c)[2]), "+f"((c)[3]) \
        : "r"((A)[0]), "r"((A)[1]), "r"((A)[2]), "r"((A)[3]), "r"((B)[0]), "r"((B)[1]))

__device__ __forceinline__ void ldsm_x4(uint32_t* r, uint32_t addr) {
    asm volatile("ldmatrix.sync.aligned.m8n8.x4.shared.b16 {%0,%1,%2,%3}, [%4];"
        : "=r"(r[0]), "=r"(r[1]), "=r"(r[2]), "=r"(r[3]) : "r"(addr));
}

// ---------------------------------------------------------------------------
// Fused prep: [0,6912) prep_x; [6912,8640) prep_w; [8640,8665) weff/beff.
// All parts read only raw kernel inputs -> one launch, no interdependency.
// ---------------------------------------------------------------------------
#define PREPX_BLOCKS 6912
#define PREPW_BLOCKS 1728
#define PREP_GRID (PREPX_BLOCKS + PREPW_BLOCKS + 25)

__global__ __launch_bounds__(256) void fused_prep(
    const float* __restrict__ X,
    const float* __restrict__ Wq, const float* __restrict__ Wk, const float* __restrict__ Wv,
    const float* __restrict__ W1, const float* __restrict__ b1,
    const float* __restrict__ bq, const float* __restrict__ bk)
{
    const int bid = blockIdx.x;
    const int tid = threadIdx.x;

    if (bid < PREPX_BLOCKS) {
        const int t = bid * 256 + tid;
        const size_t base = (size_t)t * 8;
        float4 a = *(const float4*)&X[base];
        float4 b = *(const float4*)&X[base + 4];
        __nv_bfloat16 hi[8], lo[8];
        float v[8] = {a.x,a.y,a.z,a.w,b.x,b.y,b.z,b.w};
        #pragma unroll
        for (int i = 0; i < 8; i++) {
            hi[i] = __float2bfloat16(v[i]);
            lo[i] = __float2bfloat16(v[i] - __bfloat162float(hi[i]));
        }
        *(uint4*)&g_xhi[base] = *(uint4*)hi;
        *(uint4*)&g_xlo[base] = *(uint4*)lo;
        return;
    }

    if (bid < PREPX_BLOCKS + PREPW_BLOCKS) {
        __shared__ float ts[32][33];
        const int b2 = bid - PREPX_BLOCKS;
        const int bx = b2 % 72;
        const int by = b2 / 72;
        const int which = bx / 24;
        const float* W = which == 0 ? Wq : (which == 1 ? Wk : Wv);
        const int nloc0 = (bx % 24) * 32;
        const int k0 = by * 32;
        const int tx = tid % 32, ty = tid / 32;

        #pragma unroll
        for (int r = ty; r < 32; r += 8)
            ts[r][tx] = W[(size_t)(k0 + r) * Dsz + nloc0 + tx];
        __syncthreads();
        #pragma unroll
        for (int r = ty; r < 32; r += 8) {
            float v = ts[tx][r];
            __nv_bfloat16 hi = __float2bfloat16(v);
            __nv_bfloat16 lo = __float2bfloat16(v - __bfloat162float(hi));
            size_t o = (size_t)(bx * 32 + r) * Dsz + k0 + tx;
            g_wthi[o] = hi;
            g_wtlo[o] = lo;
        }
        return;
    }

    // ---- weff/beff ----
    const int wb = bid - (PREPX_BLOCKS + PREPW_BLOCKS);
    if (wb == 24) {
        if (tid == 0) g_tile_ctr = 0;                      // reset tile queue
        for (int e = tid; e < 4 * Dsz; e += 256) {         // zero pad rows 60..63
            int o = 60 + e / Dsz, k = e % Dsz;
            g_wehi[(size_t)o * Dsz + k] = __float2bfloat16(0.f);
            g_welo[(size_t)o * Dsz + k] = __float2bfloat16(0.f);
        }
        if (tid >= 60 && tid < 64) g_beff[tid] = 0.f;      // pad beff
        const int w = tid >> 5, lane = tid & 31;
        #pragma unroll 1
        for (int o = w; o < 60; o += 8) {
            float s = 0.f;
            #pragma unroll 4
            for (int j = lane; j < Dsz; j += 32) {
                s = fmaf(bq[j], W1[(size_t)j * 60 + o], s);
                s = fmaf(bk[j], W1[(size_t)(Dsz + j) * 60 + o], s);
            }
            #pragma unroll
            for (int t = 16; t > 0; t >>= 1) s += __shfl_xor_sync(0xffffffffu, s, t);
            if (lane == 0) g_beff[o] = b1[o] + s;
        }
        return;
    }

    // Weff rows [k0, k0+32): Weff = Wq@W1[0:768] + Wk@W1[768:1536]; store ^T bf16 hi/lo
    __shared__ float As[32][33];
    __shared__ float Ws[32][64];
    const int tx = tid % 16, ty = tid / 16;
    const int k0 = wb * 32;

    float acc[2][4];
    #pragma unroll
    for (int r = 0; r < 2; r++)
        #pragma unroll
        for (int j = 0; j < 4; j++) acc[r][j] = 0.f;

    #pragma unroll 1
    for (int p = 0; p < 2; p++) {
        const float* Wsrc = p ? Wk : Wq;
        const int w1off = p * Dsz;
        #pragma unroll 1
        for (int jc = 0; jc < Dsz; jc += 32) {
            {
                int r = tid >> 3, c4 = tid & 7;
                float4 a = *(const float4*)&Wsrc[(size_t)(k0 + r) * Dsz + jc + c4 * 4];
                As[c4*4+0][r] = a.x; As[c4*4+1][r] = a.y;
                As[c4*4+2][r] = a.z; As[c4*4+3][r] = a.w;
            }
            for (int e = tid; e < 32*64; e += 256) {
                int i = e >> 6, o = e & 63;
                Ws[i][o] = (o < 60) ? W1[(size_t)(w1off + jc + i) * 60 + o] : 0.f;
            }
            __syncthreads();
            #pragma unroll
            for (int i = 0; i < 32; i++) {
                float4 w = *(const float4*)&Ws[i][tx*4];
                float a0 = As[i][ty*2], a1 = As[i][ty*2+1];
                acc[0][0] = fmaf(a0, w.x, acc[0][0]);
                acc[0][1] = fmaf(a0, w.y, acc[0][1]);
                acc[0][2] = fmaf(a0, w.z, acc[0][2]);
                acc[0][3] = fmaf(a0, w.w, acc[0][3]);
                acc[1][0] = fmaf(a1, w.x, acc[1][0]);
                acc[1][1] = fmaf(a1, w.y, acc[1][1]);
                acc[1][2] = fmaf(a1, w.z, acc[1][2]);
                acc[1][3] = fmaf(a1, w.w, acc[1][3]);
            }
            __syncthreads();
        }
    }
    #pragma unroll
    for (int r = 0; r < 2; r++)
        #pragma unroll
        for (int j = 0; j < 4; j++) {
            int o = tx*4 + j;
            if (o < 60) {
                float v = acc[r][j];
                int kk = k0 + ty*2 + r;
                __nv_bfloat16 hi = __float2bfloat16(v);
                __nv_bfloat16 lo = __float2bfloat16(v - __bfloat162float(hi));
                g_wehi[(size_t)o * Dsz + kk] = hi;
                g_welo[(size_t)o * Dsz + kk] = lo;
            }
        }
}

// ---------------------------------------------------------------------------
// Kernel 1: warp-specialized persistent GEMM (HMMA bf16x3).
// Queue: t<1296 -> QKV tile 256x128 (4x4 warps, 64x32);
//        t>=1296 -> fc1 tile 256x64  (8x2 warps, 32x32) -> relu+beff -> g_h1.
// 1 block/SM, 544 thr = 16 consumers + 1 producer. 3-stage mbarrier ring.
// Stage: Ah[0,20480) Al[20480,40960) Bh[40960,51200) Bl[51200,61440)
// ---------------------------------------------------------------------------
#define GBM 256
#define KC 32
#define PADR 40
#define STAGE_BYTES 61440
#define NST 3
#define SMEM_GEMM (128 + NST*STAGE_BYTES)
#define NQKV ((Mrows/GBM)*18)        // 1296
#define NFC1 (Mrows/GBM)             // 72
#define NTOTAL (NQKV + NFC1)         // 1368
#define NBLK 148
#define NCHUNK 24

__global__ __launch_bounds__(544, 1) void gemm_ws(
    const float* __restrict__ bq, const float* __restrict__ bk, const float* __restrict__ bv)
{
    extern __shared__ char smem[];
    __shared__ unsigned int s_tile;
    const uint32_t sb = smem_u32(smem);
    const uint32_t stbase = sb + 128;
    const int tid = threadIdx.x;
    const int wid = tid >> 5, lane = tid & 31;
    const int g = lane >> 2, tig = lane & 3;

    if (tid == 0) {
        #pragma unroll
        for (int s = 0; s < NST; s++) {
            MBARRIER_INIT(sb + s*16,     32);
            MBARRIER_INIT(sb + s*16 + 8, 16);
        }
    }
    __syncthreads();

    const int la = (lane & 7) + ((lane >> 3) & 1) * 8;
    const int ka = (lane >> 4) * 8;
    const int lb = (lane & 7) + ((lane >> 4) & 1) * 8;
    const int kb = ((lane >> 3) & 1) * 8;
    // qkv geometry (4x4)
    const int wm4 = wid & 3, wn4 = wid >> 2;
    const uint32_t aoffs4 = (uint32_t)(((wm4 * 64 + la) * PADR + ka) * 2);
    const uint32_t boffs4 = (uint32_t)(((wn4 * 32 + lb) * PADR + kb) * 2);
    // fc1 geometry (8x2)
    const int wm8 = wid & 7, wn2 = (wid >> 3) & 1;
    const uint32_t aoffs8 = (uint32_t)(((wm8 * 32 + la) * PADR + ka) * 2);
    const uint32_t boffs2 = (uint32_t)(((wn2 * 32 + lb) * PADR + kb) * 2);

    int cs = 0, cph = 0;
    int ps = 0, pph = 1;

    for (;;) {
        if (tid == 0) s_tile = atomicAdd(&g_tile_ctr, 1u);
        __syncthreads();
        const unsigned int t = s_tile;
        if (t >= NTOTAL) break;
        const bool fc1 = (t >= NQKV);
        const int m0 = fc1 ? (int)(t - NQKV) * GBM : (int)(t / 18) * GBM;
        const int ng = fc1 ? 0 : (int)(t % 18) * 128;

        if (wid == 16) {
            // ================= PRODUCER =================
            #pragma unroll 1
            for (int c = 0; c < NCHUNK; c++) {
                MBARRIER_WAIT_PARITY(sb + ps*16 + 8, pph);
                const uint32_t s0 = stbase + ps * STAGE_BYTES;
                const int kk = c * KC;
                #pragma unroll 4
                for (int i = 0; i < 32; i++) {
                    int f = lane + i * 32;
                    int r = f >> 2, j = f & 3;
                    size_t go = (size_t)(m0 + r) * Dsz + kk + j * 8;
                    uint32_t dst = s0 + (uint32_t)(r * PADR + j * 8) * 2;
                    cpa16(dst,          &g_xhi[go]);
                    cpa16(dst + 20480u, &g_xlo[go]);
                }
                if (!fc1) {
                    #pragma unroll 4
                    for (int i = 0; i < 16; i++) {
                        int f = lane + i * 32;
                        int r = f >> 2, j = f & 3;
                        size_t go = (size_t)(ng + r) * Dsz + kk + j * 8;
                        uint32_t dst = s0 + 40960u + (uint32_t)(r * PADR + j * 8) * 2;
                        cpa16(dst,          &g_wthi[go]);
                        cpa16(dst + 10240u, &g_wtlo[go]);
                    }
                } else {
                    #pragma unroll 4
                    for (int i = 0; i < 8; i++) {
                        int f = lane + i * 32;
                        int r = f >> 2, j = f & 3;        // r < 64
                        size_t go = (size_t)r * Dsz + kk + j * 8;
                        uint32_t dst = s0 + 40960u + (uint32_t)(r * PADR + j * 8) * 2;
                        cpa16(dst,          &g_wehi[go]);
                        cpa16(dst + 10240u, &g_welo[go]);
                    }
                }
                CPASYNC_MBAR_ARRIVE_NOINC(sb + ps*16);
                if (++ps == NST) { ps = 0; pph ^= 1; }
            }
        } else if (!fc1) {
            // ================= CONSUMER: QKV tile =================
            float acc[4][4][4];
            #pragma unroll
            for (int mt = 0; mt < 4; mt++)
                #pragma unroll
                for (int nt = 0; nt < 4; nt++)
                    #pragma unroll
                    for (int e = 0; e < 4; e++) acc[mt][nt][e] = 0.f;

            #pragma unroll 1
            for (int c = 0; c < NCHUNK; c++) {
                MBARRIER_WAIT_PARITY(sb + cs*16, cph);
                const uint32_t s0 = stbase + cs * STAGE_BYTES;
                const uint32_t Ah = s0 +     0u + aoffs4;
                const uint32_t Al = s0 + 20480u + aoffs4;
                const uint32_t Bh = s0 + 40960u + boffs4;
                const uint32_t Bl = s0 + 51200u + boffs4;

                #pragma unroll
                for (int ks = 0; ks < KC; ks += 16) {
                    const uint32_t ko = (uint32_t)(ks * 2);
                    uint32_t af[4][4], bh[2][4], bl[2][4];
                    #pragma unroll
                    for (int mt = 0; mt < 4; mt++)
                        ldsm_x4(af[mt], Ah + ko + (uint32_t)(mt * 16 * PADR * 2));
                    #pragma unroll
                    for (int np = 0; np < 2; np++)
                        ldsm_x4(bh[np], Bh + ko + (uint32_t)(np * 16 * PADR * 2));
                    #pragma unroll
                    for (int mt = 0; mt < 4; mt++)
                        #pragma unroll
                        for (int np = 0; np < 2; np++) {
                            MMA16816(acc[mt][np*2+0], af[mt], &bh[np][0]);
                            MMA16816(acc[mt][np*2+1], af[mt], &bh[np][2]);
                        }
                    #pragma unroll
                    for (int np = 0; np < 2; np++)
                        ldsm_x4(bl[np], Bl + ko + (uint32_t)(np * 16 * PADR * 2));
                    #pragma unroll
                    for (int mt = 0; mt < 4; mt++)
                        #pragma unroll
                        for (int np = 0; np < 2; np++) {
                            MMA16816(acc[mt][np*2+0], af[mt], &bl[np][0]);
                            MMA16816(acc[mt][np*2+1], af[mt], &bl[np][2]);
                        }
                    #pragma unroll
                    for (int mt = 0; mt < 4; mt++)
                        ldsm_x4(af[mt], Al + ko + (uint32_t)(mt * 16 * PADR * 2));
                    #pragma unroll
                    for (int mt = 0; mt < 4; mt++)
                        #pragma unroll
                        for (int np = 0; np < 2; np++) {
                            MMA16816(acc[mt][np*2+0], af[mt], &bh[np][0]);
                            MMA16816(acc[mt][np*2+1], af[mt], &bh[np][2]);
                        }
                }
                if (lane == 0) MBARRIER_ARRIVE(sb + cs*16 + 8);
                if (++cs == NST) { cs = 0; cph ^= 1; }
            }

            const int which = ng / Dsz;
            const int nloc0 = ng - which * Dsz;
            const float* bias = which == 0 ? bq : (which == 1 ? bk : bv);
            float* OUT       = which == 0 ? g_q : (which == 1 ? g_k : g_v);
            #pragma unroll
            for (int mt = 0; mt < 4; mt++) {
                const int r0 = m0 + wm4 * 64 + mt * 16 + g;
                #pragma unroll
                for (int nt = 0; nt < 4; nt++) {
                    const int nl = nloc0 + wn4 * 32 + nt * 8 + tig * 2;
                    const float b0 = __ldg(&bias[nl]), b1 = __ldg(&bias[nl + 1]);
                    float2 v0 = make_float2(acc[mt][nt][0] + b0, acc[mt][nt][1] + b1);
                    float2 v1 = make_float2(acc[mt][nt][2] + b0, acc[mt][nt][3] + b1);
                    *(float2*)&OUT[(size_t)r0       * Dsz + nl] = v0;
                    *(float2*)&OUT[(size_t)(r0 + 8) * Dsz + nl] = v1;
                }
            }
        } else {
            // ================= CONSUMER: fc1 tile (256x64) =================
            float acc[2][4][4];
            #pragma unroll
            for (int mt = 0; mt < 2; mt++)
                #pragma unroll
                for (int nt = 0; nt < 4; nt++)
                    #pragma unroll
                    for (int e = 0; e < 4; e++) acc[mt][nt][e] = 0.f;

            #pragma unroll 1
            for (int c = 0; c < NCHUNK; c++) {
                MBARRIER_WAIT_PARITY(sb + cs*16, cph);
                const uint32_t s0 = stbase + cs * STAGE_BYTES;
                const uint32_t Ah = s0 +     0u + aoffs8;
                const uint32_t Al = s0 + 20480u + aoffs8;
                const uint32_t Bh = s0 + 40960u + boffs2;
                const uint32_t Bl = s0 + 51200u + boffs2;

                #pragma unroll
                for (int ks = 0; ks < KC; ks += 16) {
                    const uint32_t ko = (uint32_t)(ks * 2);
                    uint32_t af[2][4], bh[2][4], bl[2][4];
                    #pragma unroll
                    for (int mt = 0; mt < 2; mt++)
                        ldsm_x4(af[mt], Ah + ko + (uint32_t)(mt * 16 * PADR * 2));
                    #pragma unroll
                    for (int np = 0; np < 2; np++)
                        ldsm_x4(bh[np], Bh + ko + (uint32_t)(np * 16 * PADR * 2));
                    #pragma unroll
                    for (int mt = 0; mt < 2; mt++)
                        #pragma unroll
                        for (int np = 0; np < 2; np++) {
                            MMA16816(acc[mt][np*2+0], af[mt], &bh[np][0]);
                            MMA16816(acc[mt][np*2+1], af[mt], &bh[np][2]);
                        }
                    #pragma unroll
                    for (int np = 0; np < 2; np++)
                        ldsm_x4(bl[np], Bl + ko + (uint32_t)(np * 16 * PADR * 2));
                    #pragma unroll
                    for (int mt = 0; mt < 2; mt++)
                        #pragma unroll
                        for (int np = 0; np < 2; np++) {
                            MMA16816(acc[mt][np*2+0], af[mt], &bl[np][0]);
                            MMA16816(acc[mt][np*2+1], af[mt], &bl[np][2]);
                        }
                    #pragma unroll
                    for (int mt = 0; mt < 2; mt++)
                        ldsm_x4(af[mt], Al + ko + (uint32_t)(mt * 16 * PADR * 2));
                    #pragma unroll
                    for (int mt = 0; mt < 2; mt++)
                        #pragma unroll
                        for (int np = 0; np < 2; np++) {
                            MMA16816(acc[mt][np*2+0], af[mt], &bh[np][0]);
                            MMA16816(acc[mt][np*2+1], af[mt], &bh[np][2]);
                        }
                }
                if (lane == 0) MBARRIER_ARRIVE(sb + cs*16 + 8);
                if (++cs == NST) { cs = 0; cph ^= 1; }
            }

            // epilogue: h1 = relu(acc + beff)
            #pragma unroll
            for (int mt = 0; mt < 2; mt++) {
                const int r0 = m0 + wm8 * 32 + mt * 16 + g;
                #pragma unroll
                for (int nt = 0; nt < 4; nt++) {
                    const int nl = wn2 * 32 + nt * 8 + tig * 2;
                    const float b0 = __ldg(&g_beff[nl]), b1 = __ldg(&g_beff[nl + 1]);
                    float2 v0 = make_float2(fmaxf(acc[mt][nt][0] + b0, 0.f),
                                            fmaxf(acc[mt][nt][1] + b1, 0.f));
                    float2 v1 = make_float2(fmaxf(acc[mt][nt][2] + b0, 0.f),
                                            fmaxf(acc[mt][nt][3] + b1, 0.f));
                    *(float2*)&g_h1[(size_t)r0       * 64 + nl] = v0;
                    *(float2*)&g_h1[(size_t)(r0 + 8) * 64 + nl] = v1;
                }
            }
        }
        __syncthreads();
    }
}

// ---------------------------------------------------------------------------
// Kernel 2: mlp_tail — fc2 (60->60) + relu + fc3 (60->2) + tanh from g_h1.
// 96 rows / 192 threads per block, 192 blocks.
// ---------------------------------------------------------------------------
__global__ __launch_bounds__(192) void mlp_tail(
    const float* __restrict__ W2, const float* __restrict__ b2,
    const float* __restrict__ W3, const float* __restrict__ b3)
{
    __shared__ float H[96*65];
    __shared__ float W2s[3600];
    __shared__ float W3s[120];
    __shared__ float b2s[60];
    __shared__ float b3s[2];

    const int tid = threadIdx.x;
    const int row0 = blockIdx.x * 96;

    // load h1 tile (96 x 64) -> H padded 65
    #pragma unroll
    for (int it = 0; it < 8; it++) {
        int f = tid + it * 192;          // 0..1535
        int r = f >> 4, c4 = f & 15;
        float4 a = *(const float4*)&g_h1[(size_t)(row0 + r) * 64 + c4 * 4];
        H[r*65 + c4*4 + 0] = a.x;
        H[r*65 + c4*4 + 1] = a.y;
        H[r*65 + c4*4 + 2] = a.z;
        H[r*65 + c4*4 + 3] = a.w;
    }
    for (int e = tid; e < 3600; e += 192) W2s[e] = W2[e];
    if (tid < 120) W3s[tid] = W3[tid];
    if (tid < 60)  b2s[tid] = b2[tid];
    if (tid < 2)   b3s[tid] = b3[tid];
    __syncthreads();

    // fc2: 2 threads per row, 30 outputs each
    const int row  = tid >> 1;
    const int half = tid & 1;
    float acc[30];
    #pragma unroll
    for (int j = 0; j < 30; j++) acc[j] = b2s[half*30 + j];
    #pragma unroll 4
    for (int i = 0; i < 60; i++) {
        const float hv = H[row*65 + i];
        const float* w = &W2s[i*60 + half*30];
        #pragma unroll
        for (int j = 0; j < 30; j++) acc[j] = fmaf(hv, w[j], acc[j]);
    }
    __syncthreads();
    #pragma unroll
    for (int j = 0; j < 30; j++) H[row*65 + half*30 + j] = fmaxf(acc[j], 0.f);
    __syncthreads();

    // fc3 + tanh (one thread per row)
    if (tid < 96) {
        float s0 = b3s[0], s1 = b3s[1];
        #pragma unroll 4
        for (int i = 0; i < 60; i++) {
            float h = H[tid*65 + i];
            s0 = fmaf(h, W3s[i*2 + 0], s0);
            s1 = fmaf(h, W3s[i*2 + 1], s1);
        }
        size_t rr = (size_t)(row0 + tid) * 2;
        g_sample[rr + 0] = tanhf(s0);
        g_sample[rr + 1] = tanhf(s1);
    }
}

// ---------------------------------------------------------------------------
// Kernel 3: warp-per-row grid-sample + score + gate.
// ---------------------------------------------------------------------------
__global__ __launch_bounds__(256) void sample_attn_kernel(float* __restrict__ out)
{
    const int lane = threadIdx.x & 31;
    const int row  = blockIdx.x * 8 + (threadIdx.x >> 5);
    const int b = row / Ssz;
    const int s = row % Ssz;

    const size_t sbase = (size_t)b * Ssz * 2;
    const int p0 = 2*s, p1 = 2*s + 1;
    const float gxv = (p0 < Ssz) ? g_sample[sbase + (size_t)p0*2 + 0]
                                 : g_sample[sbase + (size_t)(p0 - Ssz)*2 + 1];
    const float gyv = (p1 < Ssz) ? g_sample[sbase + (size_t)p1*2 + 0]
                                 : g_sample[sbase + (size_t)(p1 - Ssz)*2 + 1];

    const float ix = ((gxv + 1.f) * (float)Gsz - 1.f) * 0.5f;
    const float iy = ((gyv + 1.f) * (float)Gsz - 1.f) * 0.5f;
    const float x0f = floorf(ix), y0f = floorf(iy);
    const float wx1 = ix - x0f, wx0 = 1.f - wx1;
    const float wy1 = iy - y0f, wy0 = 1.f - wy1;
    const int x0 = (int)x0f, y0 = (int)y0f;
    const int x1 = x0 + 1,   y1 = y0 + 1;

    float w[4];
    int   pos[4];
    {
        const int xs[4] = {x0, x1, x0, x1};
        const int ys[4] = {y0, y0, y1, y1};
        const float ws[4] = {wx0*wy0, wx1*wy0, wx0*wy1, wx1*wy1};
        #pragma unroll
        for (int c = 0; c < 4; c++) {
            bool v = (xs[c] >= 0) && (xs[c] <= Gsz-1) && (ys[c] >= 0) && (ys[c] <= Gsz-1);
            int xc = min(max(xs[c], 0), Gsz-1);
            int yc = min(max(ys[c], 0), Gsz-1);
            pos[c] = yc * Gsz + xc;
            w[c] = v ? ws[c] : 0.f;
        }
    }

    const float4* q4 = (const float4*)(g_q + (size_t)row * Dsz);
    const float4* k4 = (const float4*)(g_k + (size_t)b * Ssz * Dsz);
    const float4* v4 = (const float4*)(g_v + (size_t)b * Ssz * Dsz);

    float part = 0.f;
    float4 sv[6];
    #pragma unroll
    for (int j = 0; j < 6; j++) {
        const int d = lane + j * 32;
        const float4 q = q4[d];
        float4 sk = make_float4(0.f,0.f,0.f,0.f);
        float4 vv = make_float4(0.f,0.f,0.f,0.f);
        #pragma unroll
        for (int c = 0; c < 4; c++) {
            const float4 kk = k4[pos[c] * 192 + d];
            const float4 vx = v4[pos[c] * 192 + d];
            sk.x = fmaf(w[c], kk.x, sk.x); sk.y = fmaf(w[c], kk.y, sk.y);
            sk.z = fmaf(w[c], kk.z, sk.z); sk.w = fmaf(w[c], kk.w, sk.w);
            vv.x = fmaf(w[c], vx.x, vv.x); vv.y = fmaf(w[c], vx.y, vv.y);
            vv.z = fmaf(w[c], vx.z, vv.z); vv.w = fmaf(w[c], vx.w, vv.w);
        }
        part += q.x*sk.x + q.y*sk.y + q.z*sk.z + q.w*sk.w;
        sv[j] = vv;
    }

    #pragma unroll
    for (int o = 16; o > 0; o >>= 1)
        part += __shfl_xor_sync(0xffffffffu, part, o);
    const float g = 1.f / (1.f + expf(-0.01f * part));

    float4* o4 = (float4*)(out + (size_t)row * Dsz);
    #pragma unroll
    for (int j = 0; j < 6; j++) {
        float4 r = sv[j];
        r.x *= g; r.y *= g; r.z *= g; r.w *= g;
        o4[lane + j * 32] = r;
    }
}

// ---------------------------------------------------------------------------
extern "C" void kernel_launch(void* const* d_in, const int* in_sizes, int n_in,
                              void* d_out, int out_size)
{
    const float* x  = (const float*)d_in[0];
    const float* Wq = (const float*)d_in[2];
    const float* bq = (const float*)d_in[3];
    const float* Wk = (const float*)d_in[4];
    const float* bk = (const float*)d_in[5];
    const float* Wv = (const float*)d_in[6];
    const float* bv = (const float*)d_in[7];
    const float* W1 = (const float*)d_in[8];
    const float* b1 = (const float*)d_in[9];
    const float* W2 = (const float*)d_in[10];
    const float* b2 = (const float*)d_in[11];
    const float* W3 = (const float*)d_in[12];
    const float* b3 = (const float*)d_in[13];

    cudaFuncSetAttribute(gemm_ws, cudaFuncAttributeMaxDynamicSharedMemorySize, SMEM_GEMM);

    fused_prep<<<PREP_GRID, 256>>>(x, Wq, Wk, Wv, W1, b1, bq, bk);   // 1 (resets tile ctr)
    gemm_ws<<<NBLK, 544, SMEM_GEMM>>>(bq, bk, bv);                   // 2 (profiled: 6th = iter2 #2)
    mlp_tail<<<Mrows / 96, 192>>>(W2, b2, W3, b3);                   // 3
    sample_attn_kernel<<<Mrows / 8, 256>>>((float*)d_out);           // 4
}

// round 11
// speedup vs baseline: 1.2140x; 1.1025x over previous
#include <cuda_runtime.h>
#include <cuda_bf16.h>
#include <math.h>
#include <cstdint>

#define Bsz 32
#define Ssz 576
#define Dsz 768
#define Gsz 24
#define Mrows (Bsz*Ssz)   // 18432
#define Ncols (3*Dsz)     // 2304

// ---------------- device scratch (allocation-free rule) ----------------
__device__ float g_q[Mrows*Dsz];
__device__ float g_k[Mrows*Dsz];
__device__ float g_v[Mrows*Dsz];
__device__ float g_sample[Mrows*2];
__device__ float g_h1[Mrows*64];
__device__ float g_beff[64];
__device__ unsigned int g_tile_ctr;
__device__ __nv_bfloat16 g_xhi[Mrows*Dsz];
__device__ __nv_bfloat16 g_xlo[Mrows*Dsz];
__device__ __nv_bfloat16 g_wthi[Ncols*Dsz];    // [Wq|Wk|Wv]^T [n][k]
__device__ __nv_bfloat16 g_wtlo[Ncols*Dsz];
__device__ __nv_bfloat16 g_wehi[64*Dsz];       // Weff^T [o][k]
__device__ __nv_bfloat16 g_welo[64*Dsz];

__device__ __forceinline__ uint32_t smem_u32(const void* p) {
    uint32_t a;
    asm("{ .reg .u64 t; cvta.to.shared.u64 t, %1; cvt.u32.u64 %0, t; }" : "=r"(a) : "l"(p));
    return a;
}
__device__ __forceinline__ void cpa16(uint32_t d, const void* s) {
    asm volatile("cp.async.cg.shared.global [%0], [%1], 16;" :: "r"(d), "l"(s));
}
#define MBARRIER_INIT(addr, cnt) \
    asm volatile("mbarrier.init.shared.b64 [%0], %1;" :: "r"((uint32_t)(addr)), "r"((uint32_t)(cnt)) : "memory")
#define MBARRIER_ARRIVE(addr) \
    asm volatile("mbarrier.arrive.shared.b64 _, [%0];" :: "r"((uint32_t)(addr)) : "memory")
#define CPASYNC_MBAR_ARRIVE_NOINC(addr) \
    asm volatile("cp.async.mbarrier.arrive.noinc.shared::cta.b64 [%0];" :: "r"((uint32_t)(addr)) : "memory")
#define MBARRIER_WAIT_PARITY(mb, par) do { \
    uint32_t _m = (uint32_t)(mb), _p = (uint32_t)(par), _d; \
    asm volatile("{\n\t.reg .pred p;\n\tmbarrier.try_wait.parity.acquire.cta.shared::cta.b64 p, [%1], %2;\n\tselp.b32 %0, 1, 0, p;\n\t}" \
        : "=r"(_d) : "r"(_m), "r"(_p) : "memory"); \
    if (!_d) { \
        asm volatile("{\n\t.reg .pred P1;\n\tWL_%=:\n\tmbarrier.try_wait.parity.acquire.cta.shared::cta.b64 P1, [%0], %1, 0x989680;\n\t@P1 bra.uni WD_%=;\n\tbra.uni WL_%=;\n\tWD_%=:\n\t}" \
            :: "r"(_m), "r"(_p) : "memory"); \
    } } while (0)

#define MMA16816(c, A, B) \
    asm volatile("mma.sync.aligned.m16n8k16.row.col.f32.bf16.bf16.f32 " \
        "{%0,%1,%2,%3},{%4,%5,%6,%7},{%8,%9},{%0,%1,%2,%3};" \
        : "+f"((c)[0]), "+f"((c)[1]), "+f"((c)[2]), "+f"((c)[3]) \
        : "r"((A)[0]), "r"((A)[1]), "r"((A)[2]), "r"((A)[3]), "r"((B)[0]), "r"((B)[1]))

__device__ __forceinline__ void ldsm_x4(uint32_t* r, uint32_t addr) {
    asm volatile("ldmatrix.sync.aligned.m8n8.x4.shared.b16 {%0,%1,%2,%3}, [%4];"
        : "=r"(r[0]), "=r"(r[1]), "=r"(r[2]), "=r"(r[3]) : "r"(addr));
}

// ---------------------------------------------------------------------------
// Fused prep: [0,6912) prep_x; [6912,8640) prep_w; [8640,8665) weff/beff.
// ---------------------------------------------------------------------------
#define PREPX_BLOCKS 6912
#define PREPW_BLOCKS 1728
#define PREP_GRID (PREPX_BLOCKS + PREPW_BLOCKS + 25)

__global__ __launch_bounds__(256) void fused_prep(
    const float* __restrict__ X,
    const float* __restrict__ Wq, const float* __restrict__ Wk, const float* __restrict__ Wv,
    const float* __restrict__ W1, const float* __restrict__ b1,
    const float* __restrict__ bq, const float* __restrict__ bk)
{
    const int bid = blockIdx.x;
    const int tid = threadIdx.x;

    if (bid < PREPX_BLOCKS) {
        const int t = bid * 256 + tid;
        const size_t base = (size_t)t * 8;
        float4 a = *(const float4*)&X[base];
        float4 b = *(const float4*)&X[base + 4];
        __nv_bfloat16 hi[8], lo[8];
        float v[8] = {a.x,a.y,a.z,a.w,b.x,b.y,b.z,b.w};
        #pragma unroll
        for (int i = 0; i < 8; i++) {
            hi[i] = __float2bfloat16(v[i]);
            lo[i] = __float2bfloat16(v[i] - __bfloat162float(hi[i]));
        }
        *(uint4*)&g_xhi[base] = *(uint4*)hi;
        *(uint4*)&g_xlo[base] = *(uint4*)lo;
        return;
    }

    if (bid < PREPX_BLOCKS + PREPW_BLOCKS) {
        __shared__ float ts[32][33];
        const int b2 = bid - PREPX_BLOCKS;
        const int bx = b2 % 72;
        const int by = b2 / 72;
        const int which = bx / 24;
        const float* W = which == 0 ? Wq : (which == 1 ? Wk : Wv);
        const int nloc0 = (bx % 24) * 32;
        const int k0 = by * 32;
        const int tx = tid % 32, ty = tid / 32;

        #pragma unroll
        for (int r = ty; r < 32; r += 8)
            ts[r][tx] = W[(size_t)(k0 + r) * Dsz + nloc0 + tx];
        __syncthreads();
        #pragma unroll
        for (int r = ty; r < 32; r += 8) {
            float v = ts[tx][r];
            __nv_bfloat16 hi = __float2bfloat16(v);
            __nv_bfloat16 lo = __float2bfloat16(v - __bfloat162float(hi));
            size_t o = (size_t)(bx * 32 + r) * Dsz + k0 + tx;
            g_wthi[o] = hi;
            g_wtlo[o] = lo;
        }
        return;
    }

    // ---- weff/beff ----
    const int wb = bid - (PREPX_BLOCKS + PREPW_BLOCKS);
    if (wb == 24) {
        if (tid == 0) g_tile_ctr = 0;
        for (int e = tid; e < 4 * Dsz; e += 256) {
            int o = 60 + e / Dsz, k = e % Dsz;
            g_wehi[(size_t)o * Dsz + k] = __float2bfloat16(0.f);
            g_welo[(size_t)o * Dsz + k] = __float2bfloat16(0.f);
        }
        if (tid >= 60 && tid < 64) g_beff[tid] = 0.f;
        const int w = tid >> 5, lane = tid & 31;
        #pragma unroll 1
        for (int o = w; o < 60; o += 8) {
            float s = 0.f;
            #pragma unroll 4
            for (int j = lane; j < Dsz; j += 32) {
                s = fmaf(bq[j], W1[(size_t)j * 60 + o], s);
                s = fmaf(bk[j], W1[(size_t)(Dsz + j) * 60 + o], s);
            }
            #pragma unroll
            for (int t = 16; t > 0; t >>= 1) s += __shfl_xor_sync(0xffffffffu, s, t);
            if (lane == 0) g_beff[o] = b1[o] + s;
        }
        return;
    }

    __shared__ float As[32][33];
    __shared__ float Ws[32][64];
    const int tx = tid % 16, ty = tid / 16;
    const int k0 = wb * 32;

    float acc[2][4];
    #pragma unroll
    for (int r = 0; r < 2; r++)
        #pragma unroll
        for (int j = 0; j < 4; j++) acc[r][j] = 0.f;

    #pragma unroll 1
    for (int p = 0; p < 2; p++) {
        const float* Wsrc = p ? Wk : Wq;
        const int w1off = p * Dsz;
        #pragma unroll 1
        for (int jc = 0; jc < Dsz; jc += 32) {
            {
                int r = tid >> 3, c4 = tid & 7;
                float4 a = *(const float4*)&Wsrc[(size_t)(k0 + r) * Dsz + jc + c4 * 4];
                As[c4*4+0][r] = a.x; As[c4*4+1][r] = a.y;
                As[c4*4+2][r] = a.z; As[c4*4+3][r] = a.w;
            }
            for (int e = tid; e < 32*64; e += 256) {
                int i = e >> 6, o = e & 63;
                Ws[i][o] = (o < 60) ? W1[(size_t)(w1off + jc + i) * 60 + o] : 0.f;
            }
            __syncthreads();
            #pragma unroll
            for (int i = 0; i < 32; i++) {
                float4 w = *(const float4*)&Ws[i][tx*4];
                float a0 = As[i][ty*2], a1 = As[i][ty*2+1];
                acc[0][0] = fmaf(a0, w.x, acc[0][0]);
                acc[0][1] = fmaf(a0, w.y, acc[0][1]);
                acc[0][2] = fmaf(a0, w.z, acc[0][2]);
                acc[0][3] = fmaf(a0, w.w, acc[0][3]);
                acc[1][0] = fmaf(a1, w.x, acc[1][0]);
                acc[1][1] = fmaf(a1, w.y, acc[1][1]);
                acc[1][2] = fmaf(a1, w.z, acc[1][2]);
                acc[1][3] = fmaf(a1, w.w, acc[1][3]);
            }
            __syncthreads();
        }
    }
    #pragma unroll
    for (int r = 0; r < 2; r++)
        #pragma unroll
        for (int j = 0; j < 4; j++) {
            int o = tx*4 + j;
            if (o < 60) {
                float v = acc[r][j];
                int kk = k0 + ty*2 + r;
                __nv_bfloat16 hi = __float2bfloat16(v);
                __nv_bfloat16 lo = __float2bfloat16(v - __bfloat162float(hi));
                g_wehi[(size_t)o * Dsz + kk] = hi;
                g_welo[(size_t)o * Dsz + kk] = lo;
            }
        }
}

// ---------------------------------------------------------------------------
// Kernel 1: warp-specialized persistent GEMM (HMMA).
// Queue: t<1296 -> QKV tile 256x128 (4x4 warps); v tiles 3-product,
//        q/k tiles 2-product (score-only precision). t>=1296 -> fc1 256x64.
// ---------------------------------------------------------------------------
#define GBM 256
#define KC 32
#define PADR 40
#define STAGE_BYTES 61440
#define NST 3
#define SMEM_GEMM (128 + NST*STAGE_BYTES)
#define NQKV ((Mrows/GBM)*18)        // 1296
#define NFC1 (Mrows/GBM)             // 72
#define NTOTAL (NQKV + NFC1)         // 1368
#define NBLK 148
#define NCHUNK 24

__global__ __launch_bounds__(544, 1) void gemm_ws(
    const float* __restrict__ bq, const float* __restrict__ bk, const float* __restrict__ bv)
{
    extern __shared__ char smem[];
    __shared__ unsigned int s_tile;
    const uint32_t sb = smem_u32(smem);
    const uint32_t stbase = sb + 128;
    const int tid = threadIdx.x;
    const int wid = tid >> 5, lane = tid & 31;
    const int g = lane >> 2, tig = lane & 3;

    if (tid == 0) {
        #pragma unroll
        for (int s = 0; s < NST; s++) {
            MBARRIER_INIT(sb + s*16,     32);
            MBARRIER_INIT(sb + s*16 + 8, 16);
        }
    }
    __syncthreads();

    const int la = (lane & 7) + ((lane >> 3) & 1) * 8;
    const int ka = (lane >> 4) * 8;
    const int lb = (lane & 7) + ((lane >> 4) & 1) * 8;
    const int kb = ((lane >> 3) & 1) * 8;
    const int wm4 = wid & 3, wn4 = wid >> 2;
    const uint32_t aoffs4 = (uint32_t)(((wm4 * 64 + la) * PADR + ka) * 2);
    const uint32_t boffs4 = (uint32_t)(((wn4 * 32 + lb) * PADR + kb) * 2);
    const int wm8 = wid & 7, wn2 = (wid >> 3) & 1;
    const uint32_t aoffs8 = (uint32_t)(((wm8 * 32 + la) * PADR + ka) * 2);
    const uint32_t boffs2 = (uint32_t)(((wn2 * 32 + lb) * PADR + kb) * 2);

    int cs = 0, cph = 0;
    int ps = 0, pph = 1;

    for (;;) {
        if (tid == 0) s_tile = atomicAdd(&g_tile_ctr, 1u);
        __syncthreads();
        const unsigned int t = s_tile;
        if (t >= NTOTAL) break;
        const bool fc1 = (t >= NQKV);
        const int m0 = fc1 ? (int)(t - NQKV) * GBM : (int)(t / 18) * GBM;
        const int ng = fc1 ? 0 : (int)(t % 18) * 128;
        const bool is_v = (!fc1) && (ng >= 2 * Dsz);   // v tiles need full precision

        if (wid == 16) {
            // ================= PRODUCER =================
            #pragma unroll 1
            for (int c = 0; c < NCHUNK; c++) {
                MBARRIER_WAIT_PARITY(sb + ps*16 + 8, pph);
                const uint32_t s0 = stbase + ps * STAGE_BYTES;
                const int kk = c * KC;
                #pragma unroll 4
                for (int i = 0; i < 32; i++) {
                    int f = lane + i * 32;
                    int r = f >> 2, j = f & 3;
                    size_t go = (size_t)(m0 + r) * Dsz + kk + j * 8;
                    uint32_t dst = s0 + (uint32_t)(r * PADR + j * 8) * 2;
                    cpa16(dst,          &g_xhi[go]);
                    cpa16(dst + 20480u, &g_xlo[go]);
                }
                if (!fc1) {
                    #pragma unroll 4
                    for (int i = 0; i < 16; i++) {
                        int f = lane + i * 32;
                        int r = f >> 2, j = f & 3;
                        size_t go = (size_t)(ng + r) * Dsz + kk + j * 8;
                        uint32_t dst = s0 + 40960u + (uint32_t)(r * PADR + j * 8) * 2;
                        cpa16(dst,          &g_wthi[go]);
                        cpa16(dst + 10240u, &g_wtlo[go]);
                    }
                } else {
                    #pragma unroll 4
                    for (int i = 0; i < 8; i++) {
                        int f = lane + i * 32;
                        int r = f >> 2, j = f & 3;
                        size_t go = (size_t)r * Dsz + kk + j * 8;
                        uint32_t dst = s0 + 40960u + (uint32_t)(r * PADR + j * 8) * 2;
                        cpa16(dst,          &g_wehi[go]);
                        cpa16(dst + 10240u, &g_welo[go]);
                    }
                }
                CPASYNC_MBAR_ARRIVE_NOINC(sb + ps*16);
                if (++ps == NST) { ps = 0; pph ^= 1; }
            }
        } else if (!fc1) {
            // ================= CONSUMER: QKV tile =================
            float acc[4][4][4];
            #pragma unroll
            for (int mt = 0; mt < 4; mt++)
                #pragma unroll
                for (int nt = 0; nt < 4; nt++)
                    #pragma unroll
                    for (int e = 0; e < 4; e++) acc[mt][nt][e] = 0.f;

            #pragma unroll 1
            for (int c = 0; c < NCHUNK; c++) {
                MBARRIER_WAIT_PARITY(sb + cs*16, cph);
                const uint32_t s0 = stbase + cs * STAGE_BYTES;
                const uint32_t Ah = s0 +     0u + aoffs4;
                const uint32_t Al = s0 + 20480u + aoffs4;
                const uint32_t Bh = s0 + 40960u + boffs4;
                const uint32_t Bl = s0 + 51200u + boffs4;

                #pragma unroll
                for (int ks = 0; ks < KC; ks += 16) {
                    const uint32_t ko = (uint32_t)(ks * 2);
                    uint32_t af[4][4], bh[2][4], bl[2][4];
                    #pragma unroll
                    for (int mt = 0; mt < 4; mt++)
                        ldsm_x4(af[mt], Ah + ko + (uint32_t)(mt * 16 * PADR * 2));
                    #pragma unroll
                    for (int np = 0; np < 2; np++)
                        ldsm_x4(bh[np], Bh + ko + (uint32_t)(np * 16 * PADR * 2));
                    #pragma unroll
                    for (int mt = 0; mt < 4; mt++)
                        #pragma unroll
                        for (int np = 0; np < 2; np++) {
                            MMA16816(acc[mt][np*2+0], af[mt], &bh[np][0]);
                            MMA16816(acc[mt][np*2+1], af[mt], &bh[np][2]);
                        }
                    #pragma unroll
                    for (int np = 0; np < 2; np++)
                        ldsm_x4(bl[np], Bl + ko + (uint32_t)(np * 16 * PADR * 2));
                    #pragma unroll
                    for (int mt = 0; mt < 4; mt++)
                        #pragma unroll
                        for (int np = 0; np < 2; np++) {
                            MMA16816(acc[mt][np*2+0], af[mt], &bl[np][0]);
                            MMA16816(acc[mt][np*2+1], af[mt], &bl[np][2]);
                        }
                    if (is_v) {   // third product only where full precision matters
                        #pragma unroll
                        for (int mt = 0; mt < 4; mt++)
                            ldsm_x4(af[mt], Al + ko + (uint32_t)(mt * 16 * PADR * 2));
                        #pragma unroll
                        for (int mt = 0; mt < 4; mt++)
                            #pragma unroll
                            for (int np = 0; np < 2; np++) {
                                MMA16816(acc[mt][np*2+0], af[mt], &bh[np][0]);
                                MMA16816(acc[mt][np*2+1], af[mt], &bh[np][2]);
                            }
                    }
                }
                if (lane == 0) MBARRIER_ARRIVE(sb + cs*16 + 8);
                if (++cs == NST) { cs = 0; cph ^= 1; }
            }

            const int which = ng / Dsz;
            const int nloc0 = ng - which * Dsz;
            const float* bias = which == 0 ? bq : (which == 1 ? bk : bv);
            float* OUT       = which == 0 ? g_q : (which == 1 ? g_k : g_v);
            #pragma unroll
            for (int mt = 0; mt < 4; mt++) {
                const int r0 = m0 + wm4 * 64 + mt * 16 + g;
                #pragma unroll
                for (int nt = 0; nt < 4; nt++) {
                    const int nl = nloc0 + wn4 * 32 + nt * 8 + tig * 2;
                    const float b0 = __ldg(&bias[nl]), b1 = __ldg(&bias[nl + 1]);
                    float2 v0 = make_float2(acc[mt][nt][0] + b0, acc[mt][nt][1] + b1);
                    float2 v1 = make_float2(acc[mt][nt][2] + b0, acc[mt][nt][3] + b1);
                    *(float2*)&OUT[(size_t)r0       * Dsz + nl] = v0;
                    *(float2*)&OUT[(size_t)(r0 + 8) * Dsz + nl] = v1;
                }
            }
        } else {
            // ================= CONSUMER: fc1 tile (256x64) =================
            float acc[2][4][4];
            #pragma unroll
            for (int mt = 0; mt < 2; mt++)
                #pragma unroll
                for (int nt = 0; nt < 4; nt++)
                    #pragma unroll
                    for (int e = 0; e < 4; e++) acc[mt][nt][e] = 0.f;

            #pragma unroll 1
            for (int c = 0; c < NCHUNK; c++) {
                MBARRIER_WAIT_PARITY(sb + cs*16, cph);
                const uint32_t s0 = stbase + cs * STAGE_BYTES;
                const uint32_t Ah = s0 +     0u + aoffs8;
                const uint32_t Al = s0 + 20480u + aoffs8;
                const uint32_t Bh = s0 + 40960u + boffs2;
                const uint32_t Bl = s0 + 51200u + boffs2;

                #pragma unroll
                for (int ks = 0; ks < KC; ks += 16) {
                    const uint32_t ko = (uint32_t)(ks * 2);
                    uint32_t af[2][4], bh[2][4], bl[2][4];
                    #pragma unroll
                    for (int mt = 0; mt < 2; mt++)
                        ldsm_x4(af[mt], Ah + ko + (uint32_t)(mt * 16 * PADR * 2));
                    #pragma unroll
                    for (int np = 0; np < 2; np++)
                        ldsm_x4(bh[np], Bh + ko + (uint32_t)(np * 16 * PADR * 2));
                    #pragma unroll
                    for (int mt = 0; mt < 2; mt++)
                        #pragma unroll
                        for (int np = 0; np < 2; np++) {
                            MMA16816(acc[mt][np*2+0], af[mt], &bh[np][0]);
                            MMA16816(acc[mt][np*2+1], af[mt], &bh[np][2]);
                        }
                    #pragma unroll
                    for (int np = 0; np < 2; np++)
                        ldsm_x4(bl[np], Bl + ko + (uint32_t)(np * 16 * PADR * 2));
                    #pragma unroll
                    for (int mt = 0; mt < 2; mt++)
                        #pragma unroll
                        for (int np = 0; np < 2; np++) {
                            MMA16816(acc[mt][np*2+0], af[mt], &bl[np][0]);
                            MMA16816(acc[mt][np*2+1], af[mt], &bl[np][2]);
                        }
                    #pragma unroll
                    for (int mt = 0; mt < 2; mt++)
                        ldsm_x4(af[mt], Al + ko + (uint32_t)(mt * 16 * PADR * 2));
                    #pragma unroll
                    for (int mt = 0; mt < 2; mt++)
                        #pragma unroll
                        for (int np = 0; np < 2; np++) {
                            MMA16816(acc[mt][np*2+0], af[mt], &bh[np][0]);
                            MMA16816(acc[mt][np*2+1], af[mt], &bh[np][2]);
                        }
                }
                if (lane == 0) MBARRIER_ARRIVE(sb + cs*16 + 8);
                if (++cs == NST) { cs = 0; cph ^= 1; }
            }

            #pragma unroll
            for (int mt = 0; mt < 2; mt++) {
                const int r0 = m0 + wm8 * 32 + mt * 16 + g;
                #pragma unroll
                for (int nt = 0; nt < 4; nt++) {
                    const int nl = wn2 * 32 + nt * 8 + tig * 2;
                    const float b0 = __ldg(&g_beff[nl]), b1 = __ldg(&g_beff[nl + 1]);
                    float2 v0 = make_float2(fmaxf(acc[mt][nt][0] + b0, 0.f),
                                            fmaxf(acc[mt][nt][1] + b1, 0.f));
                    float2 v1 = make_float2(fmaxf(acc[mt][nt][2] + b0, 0.f),
                                            fmaxf(acc[mt][nt][3] + b1, 0.f));
                    *(float2*)&g_h1[(size_t)r0       * 64 + nl] = v0;
                    *(float2*)&g_h1[(size_t)(r0 + 8) * 64 + nl] = v1;
                }
            }
        }
        __syncthreads();
    }
}

// ---------------------------------------------------------------------------
// Kernel 2: mlp_tail — fc2 + relu + fc3 + tanh from g_h1.
// ---------------------------------------------------------------------------
__global__ __launch_bounds__(192) void mlp_tail(
    const float* __restrict__ W2, const float* __restrict__ b2,
    const float* __restrict__ W3, const float* __restrict__ b3)
{
    __shared__ float H[96*65];
    __shared__ float W2s[3600];
    __shared__ float W3s[120];
    __shared__ float b2s[60];
    __shared__ float b3s[2];

    const int tid = threadIdx.x;
    const int row0 = blockIdx.x * 96;

    #pragma unroll
    for (int it = 0; it < 8; it++) {
        int f = tid + it * 192;
        int r = f >> 4, c4 = f & 15;
        float4 a = *(const float4*)&g_h1[(size_t)(row0 + r) * 64 + c4 * 4];
        H[r*65 + c4*4 + 0] = a.x;
        H[r*65 + c4*4 + 1] = a.y;
        H[r*65 + c4*4 + 2] = a.z;
        H[r*65 + c4*4 + 3] = a.w;
    }
    for (int e = tid; e < 3600; e += 192) W2s[e] = W2[e];
    if (tid < 120) W3s[tid] = W3[tid];
    if (tid < 60)  b2s[tid] = b2[tid];
    if (tid < 2)   b3s[tid] = b3[tid];
    __syncthreads();

    const int row  = tid >> 1;
    const int half = tid & 1;
    float acc[30];
    #pragma unroll
    for (int j = 0; j < 30; j++) acc[j] = b2s[half*30 + j];
    #pragma unroll 4
    for (int i = 0; i < 60; i++) {
        const float hv = H[row*65 + i];
        const float* w = &W2s[i*60 + half*30];
        #pragma unroll
        for (int j = 0; j < 30; j++) acc[j] = fmaf(hv, w[j], acc[j]);
    }
    __syncthreads();
    #pragma unroll
    for (int j = 0; j < 30; j++) H[row*65 + half*30 + j] = fmaxf(acc[j], 0.f);
    __syncthreads();

    if (tid < 96) {
        float s0 = b3s[0], s1 = b3s[1];
        #pragma unroll 4
        for (int i = 0; i < 60; i++) {
            float h = H[tid*65 + i];
            s0 = fmaf(h, W3s[i*2 + 0], s0);
            s1 = fmaf(h, W3s[i*2 + 1], s1);
        }
        size_t rr = (size_t)(row0 + tid) * 2;
        g_sample[rr + 0] = tanhf(s0);
        g_sample[rr + 1] = tanhf(s1);
    }
}

// ---------------------------------------------------------------------------
// Kernel 3: warp-per-row grid-sample + score + gate.
// ---------------------------------------------------------------------------
__global__ __launch_bounds__(256) void sample_attn_kernel(float* __restrict__ out)
{
    const int lane = threadIdx.x & 31;
    const int row  = blockIdx.x * 8 + (threadIdx.x >> 5);
    const int b = row / Ssz;
    const int s = row % Ssz;

    const size_t sbase = (size_t)b * Ssz * 2;
    const int p0 = 2*s, p1 = 2*s + 1;
    const float gxv = (p0 < Ssz) ? g_sample[sbase + (size_t)p0*2 + 0]
                                 : g_sample[sbase + (size_t)(p0 - Ssz)*2 + 1];
    const float gyv = (p1 < Ssz) ? g_sample[sbase + (size_t)p1*2 + 0]
                                 : g_sample[sbase + (size_t)(p1 - Ssz)*2 + 1];

    const float ix = ((gxv + 1.f) * (float)Gsz - 1.f) * 0.5f;
    const float iy = ((gyv + 1.f) * (float)Gsz - 1.f) * 0.5f;
    const float x0f = floorf(ix), y0f = floorf(iy);
    const float wx1 = ix - x0f, wx0 = 1.f - wx1;
    const float wy1 = iy - y0f, wy0 = 1.f - wy1;
    const int x0 = (int)x0f, y0 = (int)y0f;
    const int x1 = x0 + 1,   y1 = y0 + 1;

    float w[4];
    int   pos[4];
    {
        const int xs[4] = {x0, x1, x0, x1};
        const int ys[4] = {y0, y0, y1, y1};
        const float ws[4] = {wx0*wy0, wx1*wy0, wx0*wy1, wx1*wy1};
        #pragma unroll
        for (int c = 0; c < 4; c++) {
            bool v = (xs[c] >= 0) && (xs[c] <= Gsz-1) && (ys[c] >= 0) && (ys[c] <= Gsz-1);
            int xc = min(max(xs[c], 0), Gsz-1);
            int yc = min(max(ys[c], 0), Gsz-1);
            pos[c] = yc * Gsz + xc;
            w[c] = v ? ws[c] : 0.f;
        }
    }

    const float4* q4 = (const float4*)(g_q + (size_t)row * Dsz);
    const float4* k4 = (const float4*)(g_k + (size_t)b * Ssz * Dsz);
    const float4* v4 = (const float4*)(g_v + (size_t)b * Ssz * Dsz);

    float part = 0.f;
    float4 sv[6];
    #pragma unroll
    for (int j = 0; j < 6; j++) {
        const int d = lane + j * 32;
        const float4 q = q4[d];
        float4 sk = make_float4(0.f,0.f,0.f,0.f);
        float4 vv = make_float4(0.f,0.f,0.f,0.f);
        #pragma unroll
        for (int c = 0; c < 4; c++) {
            const float4 kk = k4[pos[c] * 192 + d];
            const float4 vx = v4[pos[c] * 192 + d];
            sk.x = fmaf(w[c], kk.x, sk.x); sk.y = fmaf(w[c], kk.y, sk.y);
            sk.z = fmaf(w[c], kk.z, sk.z); sk.w = fmaf(w[c], kk.w, sk.w);
            vv.x = fmaf(w[c], vx.x, vv.x); vv.y = fmaf(w[c], vx.y, vv.y);
            vv.z = fmaf(w[c], vx.z, vv.z); vv.w = fmaf(w[c], vx.w, vv.w);
        }
        part += q.x*sk.x + q.y*sk.y + q.z*sk.z + q.w*sk.w;
        sv[j] = vv;
    }

    #pragma unroll
    for (int o = 16; o > 0; o >>= 1)
        part += __shfl_xor_sync(0xffffffffu, part, o);
    const float g = 1.f / (1.f + expf(-0.01f * part));

    float4* o4 = (float4*)(out + (size_t)row * Dsz);
    #pragma unroll
    for (int j = 0; j < 6; j++) {
        float4 r = sv[j];
        r.x *= g; r.y *= g; r.z *= g; r.w *= g;
        o4[lane + j * 32] = r;
    }
}

// ---------------------------------------------------------------------------
extern "C" void kernel_launch(void* const* d_in, const int* in_sizes, int n_in,
                              void* d_out, int out_size)
{
    const float* x  = (const float*)d_in[0];
    const float* Wq = (const float*)d_in[2];
    const float* bq = (const float*)d_in[3];
    const float* Wk = (const float*)d_in[4];
    const float* bk = (const float*)d_in[5];
    const float* Wv = (const float*)d_in[6];
    const float* bv = (const float*)d_in[7];
    const float* W1 = (const float*)d_in[8];
    const float* b1 = (const float*)d_in[9];
    const float* W2 = (const float*)d_in[10];
    const float* b2 = (const float*)d_in[11];
    const float* W3 = (const float*)d_in[12];
    const float* b3 = (const float*)d_in[13];

    cudaFuncSetAttribute(gemm_ws, cudaFuncAttributeMaxDynamicSharedMemorySize, SMEM_GEMM);

    fused_prep<<<PREP_GRID, 256>>>(x, Wq, Wk, Wv, W1, b1, bq, bk);   // 1 (resets tile ctr)
    gemm_ws<<<NBLK, 544, SMEM_GEMM>>>(bq, bk, bv);                   // 2
    mlp_tail<<<Mrows / 96, 192>>>(W2, b2, W3, b3);                   // 3
    sample_attn_kernel<<<Mrows / 8, 256>>>((float*)d_out);           // 4
}